// round 1
// baseline (speedup 1.0000x reference)
#include <cuda_runtime.h>
#include <math.h>

// ---------------------------------------------------------------------------
// QuantumKernelMethod: 4 qubits, 2 layers.
// z(i,j) = | u_i^H M_j u_i |,  u_i = A(a_i)|0>,  M_j = A(b_j) Z0 A(b_j)^H.
// Reduced to real SGEMM over 256-dim Hermitian feature vectors.
// ---------------------------------------------------------------------------

#define NQ 16            // state dimension 2^4
#define NROWS 1024
#define FDIM 256

__device__ float g_F[NROWS * FDIM];    // row features  [i][t]
__device__ float g_Gt[FDIM * NROWS];   // col features, transposed [t][j]

// ---- gate helpers on a 16-amplitude register statevector -------------------
// wire w -> bit mask m = 8 >> w  (flat idx = b0*8 + b1*4 + b2*2 + b3)

__device__ __forceinline__ void gate_ry(float2* st, int m, float t) {
    float s, c; sincosf(0.5f * t, &s, &c);
#pragma unroll
    for (int idx = 0; idx < 16; idx++) {
        if (!(idx & m)) {
            float2 x0 = st[idx], x1 = st[idx | m];
            st[idx]     = make_float2(c * x0.x - s * x1.x, c * x0.y - s * x1.y);
            st[idx | m] = make_float2(s * x0.x + c * x1.x, s * x0.y + c * x1.y);
        }
    }
}

__device__ __forceinline__ void gate_rx(float2* st, int m, float t) {
    float s, c; sincosf(0.5f * t, &s, &c);
#pragma unroll
    for (int idx = 0; idx < 16; idx++) {
        if (!(idx & m)) {
            float2 x0 = st[idx], x1 = st[idx | m];
            // new0 = c*x0 - i s * x1 ; new1 = -i s * x0 + c*x1
            st[idx]     = make_float2(c * x0.x + s * x1.y, c * x0.y - s * x1.x);
            st[idx | m] = make_float2(c * x1.x + s * x0.y, c * x1.y - s * x0.x);
        }
    }
}

__device__ __forceinline__ void gate_rz(float2* st, int m, float t) {
    float s, c; sincosf(0.5f * t, &s, &c);
#pragma unroll
    for (int idx = 0; idx < 16; idx++) {
        if (!(idx & m)) {
            float2 x0 = st[idx], x1 = st[idx | m];
            // x0 *= e^{-i t/2} = (c, -s); x1 *= e^{+i t/2} = (c, s)
            st[idx]     = make_float2(c * x0.x + s * x0.y, c * x0.y - s * x0.x);
            st[idx | m] = make_float2(c * x1.x - s * x1.y, c * x1.y + s * x1.x);
        }
    }
}

__device__ __forceinline__ void gate_cnot(float2* st, int mc, int mt) {
#pragma unroll
    for (int idx = 0; idx < 16; idx++) {
        if ((idx & mc) && !(idx & mt)) {
            float2 tmp = st[idx];
            st[idx] = st[idx | mt];
            st[idx | mt] = tmp;
        }
    }
}

__device__ __forceinline__ void apply_ansatz(float2* st, const float* vec,
                                             const float* params) {
#pragma unroll
    for (int i = 0; i < 4; i++) gate_ry(st, 8 >> i, vec[i]);
#pragma unroll
    for (int l = 0; l < 2; l++) {
#pragma unroll
        for (int i = 0; i < 4; i++) {
            const float* p = params + (l * 4 + i) * 3;
            gate_rx(st, 8 >> i, p[0]);
            gate_ry(st, 8 >> i, p[1]);
            gate_rz(st, 8 >> i, p[2]);
        }
        gate_cnot(st, 8, 4);  // (0,1)
        gate_cnot(st, 4, 2);  // (1,2)
        gate_cnot(st, 2, 1);  // (2,3)
        gate_cnot(st, 1, 8);  // (3,0)
    }
}

// ---- Kernel A: feature rows from u_i = A(a_i)|0> ---------------------------
__global__ void build_F(const float* __restrict__ a,
                        const float* __restrict__ params, int n) {
    int i = blockIdx.x * blockDim.x + threadIdx.x;
    if (i >= n) return;

    float vec[4];
#pragma unroll
    for (int q = 0; q < 4; q++) vec[q] = a[i * 4 + q];

    float2 u[16];
#pragma unroll
    for (int k = 0; k < 16; k++) u[k] = make_float2(0.f, 0.f);
    u[0] = make_float2(1.f, 0.f);

    apply_ansatz(u, vec, params);

    float* F = g_F + (size_t)i * FDIM;
#pragma unroll
    for (int p = 0; p < 16; p++)
        F[p] = u[p].x * u[p].x + u[p].y * u[p].y;

    int idx = 0;
#pragma unroll
    for (int p = 0; p < 16; p++) {
#pragma unroll
        for (int q = p + 1; q < 16; q++) {
            float re = u[p].x * u[q].x + u[p].y * u[q].y;  // Re(u_p conj(u_q))
            float im = u[p].y * u[q].x - u[p].x * u[q].y;  // Im(u_p conj(u_q))
            F[16 + idx]  = 2.f * re;
            F[136 + idx] = 2.f * im;
            idx++;
        }
    }
}

// ---- Kernel B: feature cols from M_j = A(b_j) Z0 A(b_j)^H ------------------
// 4 j's per 64-thread block; 16 lanes per j, lane k simulates column k.
__global__ void build_G(const float* __restrict__ b,
                        const float* __restrict__ params, int n) {
    __shared__ float2 sh[4][16][16];  // [jj][row p][col k]

    int tid = threadIdx.x;
    int jj = tid >> 4;            // 0..3
    int lane = tid & 15;          // 0..15
    int j = blockIdx.x * 4 + jj;
    if (j >= n) return;

    float vec[4];
#pragma unroll
    for (int q = 0; q < 4; q++) vec[q] = b[j * 4 + q];

    float2 st[16];
#pragma unroll
    for (int k = 0; k < 16; k++) st[k] = make_float2(0.f, 0.f);
    st[lane] = make_float2(1.f, 0.f);

    apply_ansatz(st, vec, params);

#pragma unroll
    for (int p = 0; p < 16; p++) sh[jj][p][lane] = st[p];
    __syncthreads();

    // lane == p computes diag M_pp and off-diag M_pq for q > p
    int p = lane;
    float d = 0.f;
#pragma unroll
    for (int k = 0; k < 16; k++) {
        float s = (k < 8) ? 1.f : -1.f;
        float2 ap = sh[jj][p][k];
        d += s * (ap.x * ap.x + ap.y * ap.y);
    }
    g_Gt[p * NROWS + j] = d;

    // linear pair index base for row p: 15p - p(p-1)/2
    int idx = 15 * p - (p * (p - 1)) / 2;
    for (int q = p + 1; q < 16; q++) {
        float re = 0.f, im = 0.f;
#pragma unroll
        for (int k = 0; k < 16; k++) {
            float s = (k < 8) ? 1.f : -1.f;
            float2 ap = sh[jj][p][k];
            float2 aq = sh[jj][q][k];
            re += s * (ap.x * aq.x + ap.y * aq.y);
            im += s * (ap.y * aq.x - ap.x * aq.y);
        }
        g_Gt[(16 + idx) * NROWS + j]  = re;
        g_Gt[(136 + idx) * NROWS + j] = im;
        idx++;
    }
}

// ---- Kernel C: C[i][j] = | sum_t F[i][t] * Gt[t][j] | ----------------------
// 64x64 tile, 256 threads, 4x4 register blocking, k-tile 16.
#define BM 64
#define BN 64
#define BK 16

__global__ __launch_bounds__(256) void gemm_abs(float* __restrict__ C) {
    __shared__ float As[BK][BM + 1];
    __shared__ float Bs[BK][BN];

    int tid = threadIdx.x;
    int tx = tid & 15;        // 0..15 -> 4 cols each
    int ty = tid >> 4;        // 0..15 -> 4 rows each
    int i0 = blockIdx.y * BM;
    int j0 = blockIdx.x * BN;

    float acc[4][4];
#pragma unroll
    for (int r = 0; r < 4; r++)
#pragma unroll
        for (int c = 0; c < 4; c++) acc[r][c] = 0.f;

    for (int kt = 0; kt < FDIM; kt += BK) {
        {   // load A tile 64x16: one float4 per thread
            int row = tid >> 2, seg = tid & 3;
            float4 v = *(const float4*)&g_F[(size_t)(i0 + row) * FDIM + kt + seg * 4];
            As[seg * 4 + 0][row] = v.x;
            As[seg * 4 + 1][row] = v.y;
            As[seg * 4 + 2][row] = v.z;
            As[seg * 4 + 3][row] = v.w;
        }
        {   // load B tile 16x64: one float4 per thread
            int krow = tid >> 4, seg = tid & 15;
            float4 v = *(const float4*)&g_Gt[(size_t)(kt + krow) * NROWS + j0 + seg * 4];
            *(float4*)&Bs[krow][seg * 4] = v;
        }
        __syncthreads();

#pragma unroll
        for (int k = 0; k < BK; k++) {
            float areg[4], breg[4];
#pragma unroll
            for (int r = 0; r < 4; r++) areg[r] = As[k][ty * 4 + r];
#pragma unroll
            for (int c = 0; c < 4; c++) breg[c] = Bs[k][tx * 4 + c];
#pragma unroll
            for (int r = 0; r < 4; r++)
#pragma unroll
                for (int c = 0; c < 4; c++) acc[r][c] += areg[r] * breg[c];
        }
        __syncthreads();
    }

#pragma unroll
    for (int r = 0; r < 4; r++) {
        float4 o = make_float4(fabsf(acc[r][0]), fabsf(acc[r][1]),
                               fabsf(acc[r][2]), fabsf(acc[r][3]));
        *(float4*)&C[(size_t)(i0 + ty * 4 + r) * NROWS + j0 + tx * 4] = o;
    }
}

// ---------------------------------------------------------------------------
extern "C" void kernel_launch(void* const* d_in, const int* in_sizes, int n_in,
                              void* d_out, int out_size) {
    const float* a = (const float*)d_in[0];       // [1024,4]
    const float* b = (const float*)d_in[1];       // [1024,4]
    const float* params = (const float*)d_in[2];  // [2,4,3]
    float* out = (float*)d_out;                   // [1024,1024]

    int na = in_sizes[0] / 4;   // 1024
    int nb = in_sizes[1] / 4;   // 1024

    build_F<<<(na + 255) / 256, 256>>>(a, params, na);
    build_G<<<(nb + 3) / 4, 64>>>(b, params, nb);

    dim3 grid(NROWS / BN, NROWS / BM);
    gemm_abs<<<grid, 256>>>(out);
}

// round 2
// speedup vs baseline: 2.3732x; 2.3732x over previous
#include <cuda_runtime.h>
#include <math.h>

// ---------------------------------------------------------------------------
// QuantumKernelMethod: 4 qubits, 2 layers.
// z(i,j) = | u_i^H M_j u_i |,  u_i = A(a_i)|0>,  M_j = A(b_j) Z0 A(b_j)^H.
// Reduced to real NT-SGEMM over 256-dim Hermitian feature vectors:
//   C = | F [1024x256] * G^T [256x1024] |
// ---------------------------------------------------------------------------

#define NROWS 1024
#define FDIM 256

__device__ float g_F[NROWS * FDIM];   // row features  [i][t]
__device__ float g_G[NROWS * FDIM];   // col features  [j][t]  (row-major, NT gemm)

// ---- gate helpers on a 16-amplitude register statevector -------------------
// wire w -> bit mask m = 8 >> w  (flat idx = b0*8 + b1*4 + b2*2 + b3)

__device__ __forceinline__ void gate_ry(float2* st, int m, float t) {
    float s, c; __sincosf(0.5f * t, &s, &c);
#pragma unroll
    for (int idx = 0; idx < 16; idx++) {
        if (!(idx & m)) {
            float2 x0 = st[idx], x1 = st[idx | m];
            st[idx]     = make_float2(c * x0.x - s * x1.x, c * x0.y - s * x1.y);
            st[idx | m] = make_float2(s * x0.x + c * x1.x, s * x0.y + c * x1.y);
        }
    }
}

__device__ __forceinline__ void gate_rx(float2* st, int m, float t) {
    float s, c; __sincosf(0.5f * t, &s, &c);
#pragma unroll
    for (int idx = 0; idx < 16; idx++) {
        if (!(idx & m)) {
            float2 x0 = st[idx], x1 = st[idx | m];
            st[idx]     = make_float2(c * x0.x + s * x1.y, c * x0.y - s * x1.x);
            st[idx | m] = make_float2(c * x1.x + s * x0.y, c * x1.y - s * x0.x);
        }
    }
}

__device__ __forceinline__ void gate_rz(float2* st, int m, float t) {
    float s, c; __sincosf(0.5f * t, &s, &c);
#pragma unroll
    for (int idx = 0; idx < 16; idx++) {
        if (!(idx & m)) {
            float2 x0 = st[idx], x1 = st[idx | m];
            st[idx]     = make_float2(c * x0.x + s * x0.y, c * x0.y - s * x0.x);
            st[idx | m] = make_float2(c * x1.x - s * x1.y, c * x1.y + s * x1.x);
        }
    }
}

__device__ __forceinline__ void gate_cnot(float2* st, int mc, int mt) {
#pragma unroll
    for (int idx = 0; idx < 16; idx++) {
        if ((idx & mc) && !(idx & mt)) {
            float2 tmp = st[idx];
            st[idx] = st[idx | mt];
            st[idx | mt] = tmp;
        }
    }
}

__device__ __forceinline__ void apply_ansatz(float2* st, const float* vec,
                                             const float* params) {
#pragma unroll
    for (int i = 0; i < 4; i++) gate_ry(st, 8 >> i, vec[i]);
#pragma unroll
    for (int l = 0; l < 2; l++) {
#pragma unroll
        for (int i = 0; i < 4; i++) {
            const float* p = params + (l * 4 + i) * 3;
            gate_rx(st, 8 >> i, p[0]);
            gate_ry(st, 8 >> i, p[1]);
            gate_rz(st, 8 >> i, p[2]);
        }
        gate_cnot(st, 8, 4);
        gate_cnot(st, 4, 2);
        gate_cnot(st, 2, 1);
        gate_cnot(st, 1, 8);
    }
}

// idx in [0,120) -> (p,q), p<q<16, p-major enumeration
__device__ __forceinline__ void find_pq(int idx, int& p, int& q) {
    p = 0;
    while (idx >= 15 - p) { idx -= 15 - p; p++; }
    q = p + 1 + idx;
}

// ---- Kernel A: feature rows from u_i = A(a_i)|0>, one warp per row ---------
__global__ __launch_bounds__(256) void build_F(const float* __restrict__ a,
                                               const float* __restrict__ params,
                                               int n) {
    __shared__ float2 sh_u[8][16];
    int w = threadIdx.x >> 5, lane = threadIdx.x & 31;
    int i = blockIdx.x * 8 + w;
    if (i >= n) return;

    float vec[4];
#pragma unroll
    for (int q = 0; q < 4; q++) vec[q] = a[i * 4 + q];

    float2 u[16];
#pragma unroll
    for (int k = 0; k < 16; k++) u[k] = make_float2(0.f, 0.f);
    u[0] = make_float2(1.f, 0.f);

    apply_ansatz(u, vec, params);   // all 32 lanes redundantly

    if (lane == 0) {
#pragma unroll
        for (int k = 0; k < 16; k++) sh_u[w][k] = u[k];
    }
    __syncwarp();

    float* F = g_F + (size_t)i * FDIM;
#pragma unroll
    for (int kk = 0; kk < 8; kk++) {
        int t = lane + 32 * kk;
        float f;
        if (t < 16) {
            float2 v = sh_u[w][t];
            f = v.x * v.x + v.y * v.y;
        } else {
            int idx = (t < 136) ? (t - 16) : (t - 136);
            int p, q; find_pq(idx, p, q);
            float2 up = sh_u[w][p], uq = sh_u[w][q];
            if (t < 136) f = 2.f * (up.x * uq.x + up.y * uq.y);  // 2 Re(u_p conj u_q)
            else         f = 2.f * (up.y * uq.x - up.x * uq.y);  // 2 Im(u_p conj u_q)
        }
        F[t] = f;   // coalesced across lanes
    }
}

// ---- Kernel B: feature rows from M_j = A(b_j) Z0 A(b_j)^H ------------------
// 8 j's per 128-thread block; 16 lanes per j, lane k simulates column k.
__global__ __launch_bounds__(128) void build_G(const float* __restrict__ b,
                                               const float* __restrict__ params,
                                               int n) {
    __shared__ float2 sh_st[8][16][17];  // [group][row p][col k], padded
    __shared__ float  sh_f[8][256];

    int tid = threadIdx.x;
    int g = tid >> 4;          // 0..7
    int l = tid & 15;          // 0..15
    int j = blockIdx.x * 8 + g;
    if (j >= n) j = n - 1;     // duplicate work for tail; writes guarded below

    float vec[4];
#pragma unroll
    for (int q = 0; q < 4; q++) vec[q] = b[j * 4 + q];

    float2 st[16];
#pragma unroll
    for (int k = 0; k < 16; k++) st[k] = make_float2(0.f, 0.f);
    st[l] = make_float2(1.f, 0.f);

    apply_ansatz(st, vec, params);

#pragma unroll
    for (int p = 0; p < 16; p++) sh_st[g][p][l] = st[p];
    __syncthreads();

    // diagonal: M_pp = sum_k z_k |A[p][k]|^2, z_k = +1 if k<8 else -1
    {
        float d = 0.f;
#pragma unroll
        for (int k = 0; k < 16; k++) {
            float zk = (k < 8) ? 1.f : -1.f;
            float2 v = sh_st[g][l][k];
            d += zk * (v.x * v.x + v.y * v.y);
        }
        sh_f[g][l] = d;
    }

    // off-diagonals: balanced lane-strided distribution of the 120 pairs
    for (int idx = l; idx < 120; idx += 16) {
        int p, q; find_pq(idx, p, q);
        float re = 0.f, im = 0.f;
#pragma unroll
        for (int k = 0; k < 16; k++) {
            float zk = (k < 8) ? 1.f : -1.f;
            float2 ap = sh_st[g][p][k];
            float2 aq = sh_st[g][q][k];
            re += zk * (ap.x * aq.x + ap.y * aq.y);   // Re(A_pk conj A_qk)
            im += zk * (ap.y * aq.x - ap.x * aq.y);   // Im(A_pk conj A_qk)
        }
        sh_f[g][16 + idx]  = re;
        sh_f[g][136 + idx] = im;
    }
    __syncthreads();

    // coalesced block write: 8 x 256 floats, row-major [j][t]
#pragma unroll
    for (int it = 0; it < 16; it++) {
        int flat = it * 128 + tid;
        int jl = flat >> 8, t = flat & 255;
        int jg = blockIdx.x * 8 + jl;
        if (jg < n) g_G[(size_t)jg * FDIM + t] = sh_f[jl][t];
    }
}

// ---- Kernel C: C[i][j] = | sum_t F[i][t] * G[j][t] |  (NT GEMM) ------------
// 128x64 tile, 256 threads, 8x4 register microtile, BK=16, float4 LDS.
#define BM 128
#define BN 64
#define BK 16

__global__ __launch_bounds__(256) void gemm_abs(float* __restrict__ C) {
    __shared__ float As[BK][BM + 4];
    __shared__ float Bs[BK][BN + 4];

    int tid = threadIdx.x;
    int tx = tid & 15;        // 0..15 -> 4 cols each (64)
    int ty = tid >> 4;        // 0..15 -> 8 rows each (128)
    int i0 = blockIdx.y * BM;
    int j0 = blockIdx.x * BN;

    float acc[8][4];
#pragma unroll
    for (int r = 0; r < 8; r++)
#pragma unroll
        for (int c = 0; c < 4; c++) acc[r][c] = 0.f;

    for (int kt = 0; kt < FDIM; kt += BK) {
        // A tile: 128 rows x 16 k = 512 float4, 2 per thread, store transposed
#pragma unroll
        for (int v = tid; v < 512; v += 256) {
            int row = v >> 2, seg = v & 3;
            float4 f = *(const float4*)&g_F[(size_t)(i0 + row) * FDIM + kt + seg * 4];
            As[seg * 4 + 0][row] = f.x;
            As[seg * 4 + 1][row] = f.y;
            As[seg * 4 + 2][row] = f.z;
            As[seg * 4 + 3][row] = f.w;
        }
        // B tile: 64 rows(j) x 16 k = 256 float4, 1 per thread, store transposed
        {
            int row = tid >> 2, seg = tid & 3;
            float4 f = *(const float4*)&g_G[(size_t)(j0 + row) * FDIM + kt + seg * 4];
            Bs[seg * 4 + 0][row] = f.x;
            Bs[seg * 4 + 1][row] = f.y;
            Bs[seg * 4 + 2][row] = f.z;
            Bs[seg * 4 + 3][row] = f.w;
        }
        __syncthreads();

#pragma unroll
        for (int k = 0; k < BK; k++) {
            float4 a0 = *(const float4*)&As[k][ty * 8];
            float4 a1 = *(const float4*)&As[k][ty * 8 + 4];
            float4 bb = *(const float4*)&Bs[k][tx * 4];
            float ar[8] = {a0.x, a0.y, a0.z, a0.w, a1.x, a1.y, a1.z, a1.w};
            float br[4] = {bb.x, bb.y, bb.z, bb.w};
#pragma unroll
            for (int r = 0; r < 8; r++)
#pragma unroll
                for (int c = 0; c < 4; c++) acc[r][c] += ar[r] * br[c];
        }
        __syncthreads();
    }

#pragma unroll
    for (int r = 0; r < 8; r++) {
        float4 o = make_float4(fabsf(acc[r][0]), fabsf(acc[r][1]),
                               fabsf(acc[r][2]), fabsf(acc[r][3]));
        *(float4*)&C[(size_t)(i0 + ty * 8 + r) * NROWS + j0 + tx * 4] = o;
    }
}

// ---------------------------------------------------------------------------
extern "C" void kernel_launch(void* const* d_in, const int* in_sizes, int n_in,
                              void* d_out, int out_size) {
    const float* a = (const float*)d_in[0];       // [1024,4]
    const float* b = (const float*)d_in[1];       // [1024,4]
    const float* params = (const float*)d_in[2];  // [2,4,3]
    float* out = (float*)d_out;                   // [1024,1024]

    int na = in_sizes[0] / 4;
    int nb = in_sizes[1] / 4;

    build_F<<<(na + 7) / 8, 256>>>(a, params, na);
    build_G<<<(nb + 7) / 8, 128>>>(b, params, nb);

    dim3 grid(NROWS / BN, NROWS / BM);   // (16, 8) = 128 blocks, 1 wave
    gemm_abs<<<grid, 256>>>(out);
}

// round 4
// speedup vs baseline: 3.3704x; 1.4202x over previous
#include <cuda_runtime.h>
#include <math.h>
#include <stdint.h>

// ---------------------------------------------------------------------------
// QuantumKernelMethod: 4 qubits, 2 layers.
// z(i,j) = | u_i^H M_j u_i |,  u_i = A(a_i)|0>,  M_j = A(b_j) Z0 A(b_j)^H.
// Reduced to real NT-GEMM over 256-dim Hermitian feature vectors (tf32 MMA):
//   C = | F [1024x256] * G^T [256x1024] |
// ---------------------------------------------------------------------------

#define NROWS 1024
#define FDIM 256

__device__ float g_F[NROWS * FDIM];   // row features [i][t], tf32-rounded
__device__ float g_G[NROWS * FDIM];   // col features [j][t], tf32-rounded

__device__ __forceinline__ float to_tf32(float x) {
    float r;
    asm("cvt.rna.tf32.f32 %0, %1;" : "=f"(r) : "f"(x));
    return r;
}

// ---- fused 1q gate application ---------------------------------------------
// state flat idx = b0*8 + b1*4 + b2*2 + b3 ; wire w -> mask 8>>w

__device__ __forceinline__ void gate_ry_real(float2* st, int m, float c, float s) {
#pragma unroll
    for (int idx = 0; idx < 16; idx++) {
        if (!(idx & m)) {
            float2 x0 = st[idx], x1 = st[idx | m];
            st[idx]     = make_float2(c * x0.x - s * x1.x, c * x0.y - s * x1.y);
            st[idx | m] = make_float2(s * x0.x + c * x1.x, s * x0.y + c * x1.y);
        }
    }
}

// generic complex 2x2: new0 = u00 x0 + u01 x1 ; new1 = u10 x0 + u11 x1
__device__ __forceinline__ void gate_u2(float2* st, int m,
                                        float2 u00, float2 u01,
                                        float2 u10, float2 u11) {
#pragma unroll
    for (int idx = 0; idx < 16; idx++) {
        if (!(idx & m)) {
            float2 x0 = st[idx], x1 = st[idx | m];
            float2 n0, n1;
            n0.x = u00.x * x0.x - u00.y * x0.y + u01.x * x1.x - u01.y * x1.y;
            n0.y = u00.x * x0.y + u00.y * x0.x + u01.x * x1.y + u01.y * x1.x;
            n1.x = u10.x * x0.x - u10.y * x0.y + u11.x * x1.x - u11.y * x1.y;
            n1.y = u10.x * x0.y + u10.y * x0.x + u11.x * x1.y + u11.y * x1.x;
            st[idx] = n0;
            st[idx | m] = n1;
        }
    }
}

__device__ __forceinline__ void gate_cnot(float2* st, int mc, int mt) {
#pragma unroll
    for (int idx = 0; idx < 16; idx++) {
        if ((idx & mc) && !(idx & mt)) {
            float2 tmp = st[idx];
            st[idx] = st[idx | mt];
            st[idx | mt] = tmp;
        }
    }
}

// ansatz with precomputed per-(layer,qubit) fused 2x2 matrices shU[8][4]
__device__ __forceinline__ void apply_ansatz_fused(float2* st, const float* vec,
                                                   const float2 (*shU)[4]) {
#pragma unroll
    for (int i = 0; i < 4; i++) {
        float s, c; __sincosf(0.5f * vec[i], &s, &c);
        gate_ry_real(st, 8 >> i, c, s);
    }
#pragma unroll
    for (int l = 0; l < 2; l++) {
#pragma unroll
        for (int i = 0; i < 4; i++) {
            const float2* U = shU[l * 4 + i];
            gate_u2(st, 8 >> i, U[0], U[1], U[2], U[3]);  // broadcast LDS
        }
        gate_cnot(st, 8, 4);
        gate_cnot(st, 4, 2);
        gate_cnot(st, 2, 1);
        gate_cnot(st, 1, 8);
    }
}

// compute fused U(l,i) = Rz(c) Ry(b) Rx(a) into shared; lanes 0..7, one each
__device__ __forceinline__ void build_fused_mats(const float* params,
                                                 float2 (*shU)[4], int tid) {
    if (tid < 8) {
        float a = params[tid * 3 + 0], b = params[tid * 3 + 1], c = params[tid * 3 + 2];
        float sa, ca, sb, cb, sc, cc;
        __sincosf(0.5f * a, &sa, &ca);
        __sincosf(0.5f * b, &sb, &cb);
        __sincosf(0.5f * c, &sc, &cc);
        // RyRx
        float2 m00 = make_float2(cb * ca,  sb * sa);
        float2 m01 = make_float2(-sb * ca, -cb * sa);
        float2 m10 = make_float2(sb * ca, -cb * sa);
        float2 m11 = make_float2(cb * ca, -sb * sa);
        // row0 *= e^{-ic/2} = (cc,-sc) ; row1 *= (cc,sc)
        shU[tid][0] = make_float2(cc * m00.x + sc * m00.y, cc * m00.y - sc * m00.x);
        shU[tid][1] = make_float2(cc * m01.x + sc * m01.y, cc * m01.y - sc * m01.x);
        shU[tid][2] = make_float2(cc * m10.x - sc * m10.y, cc * m10.y + sc * m10.x);
        shU[tid][3] = make_float2(cc * m11.x - sc * m11.y, cc * m11.y + sc * m11.x);
    }
}

// idx in [0,120) -> (p,q), p<q<16, p-major
__device__ __forceinline__ void find_pq(int idx, int& p, int& q) {
    p = 0;
    while (idx >= 15 - p) { idx -= 15 - p; p++; }
    q = p + 1 + idx;
}

// classify feature slot t in [0,256): returns packed p|q<<8|type<<16
__device__ __forceinline__ int classify_t(int t) {
    if (t < 16) return t | (t << 8) | (0 << 16);
    int idx = (t < 136) ? (t - 16) : (t - 136);
    int p, q; find_pq(idx, p, q);
    return p | (q << 8) | (((t < 136) ? 1 : 2) << 16);
}

// ---- fused precompute kernel ------------------------------------------------
// blocks [0, 8)          : F-mode, 128 rows per block, thread-per-row
// blocks [8, 8+128)      : G-mode, 8 j's per block, 16 threads per j
#define F_BLOCKS 8
#define G_BLOCKS 128

__global__ __launch_bounds__(128) void build_features(const float* __restrict__ a,
                                                      const float* __restrict__ b,
                                                      const float* __restrict__ params) {
    __shared__ float2 shU[8][4];
    int tid = threadIdx.x;
    build_fused_mats(params, shU, tid);
    __syncthreads();

    if (blockIdx.x < F_BLOCKS) {
        // ------------------- F mode -------------------
        __shared__ float2 sh_u[128][17];   // padded rows of u (16 used)

        int i = blockIdx.x * 128 + tid;
        float vec[4];
        {
            float4 v = *(const float4*)&a[i * 4];
            vec[0] = v.x; vec[1] = v.y; vec[2] = v.z; vec[3] = v.w;
        }

        float2 u[16];
#pragma unroll
        for (int k = 0; k < 16; k++) u[k] = make_float2(0.f, 0.f);
        u[0] = make_float2(1.f, 0.f);

        apply_ansatz_fused(u, vec, shU);

#pragma unroll
        for (int k = 0; k < 16; k++) sh_u[tid][k] = u[k];
        __syncthreads();

        // warp-cooperative feature extraction: warp w handles rows 32w..32w+31
        int w = tid >> 5, lane = tid & 31;
        int pqmap[8];
#pragma unroll
        for (int k = 0; k < 8; k++) pqmap[k] = classify_t(lane + 32 * k);

        int rbase = w * 32;
        for (int r = 0; r < 32; r++) {
            const float2* ur = sh_u[rbase + r];
            float* F = g_F + (size_t)(blockIdx.x * 128 + rbase + r) * FDIM;
#pragma unroll
            for (int k = 0; k < 8; k++) {
                int pk = pqmap[k];
                int p = pk & 255, q = (pk >> 8) & 255, ty = pk >> 16;
                float2 up = ur[p], uq = ur[q];
                float f;
                if (ty == 0)      f = up.x * up.x + up.y * up.y;
                else if (ty == 1) f = 2.f * (up.x * uq.x + up.y * uq.y);
                else              f = 2.f * (up.y * uq.x - up.x * uq.y);
                F[lane + 32 * k] = to_tf32(f);
            }
        }
    } else {
        // ------------------- G mode -------------------
        __shared__ float2 sh_st[8][16][17];  // [group][row p][col k]
        __shared__ float  sh_f[8][256];

        int g = tid >> 4;          // 0..7
        int l = tid & 15;          // 0..15
        int j = (blockIdx.x - F_BLOCKS) * 8 + g;

        float vec[4];
        {
            float4 v = *(const float4*)&b[j * 4];
            vec[0] = v.x; vec[1] = v.y; vec[2] = v.z; vec[3] = v.w;
        }

        float2 st[16];
#pragma unroll
        for (int k = 0; k < 16; k++) st[k] = make_float2(0.f, 0.f);
        st[l] = make_float2(1.f, 0.f);

        apply_ansatz_fused(st, vec, shU);   // column l of A(b_j)

#pragma unroll
        for (int p = 0; p < 16; p++) sh_st[g][p][l] = st[p];
        __syncthreads();

        // diagonal: M_pp = sum_k z_k |A[p][k]|^2
        {
            float d = 0.f;
#pragma unroll
            for (int k = 0; k < 16; k++) {
                float zk = (k < 8) ? 1.f : -1.f;
                float2 v = sh_st[g][l][k];
                d += zk * (v.x * v.x + v.y * v.y);
            }
            sh_f[g][l] = d;
        }

        // off-diagonals: lane-strided pairs, pq precomputed
        int pqmap[8], npair = 0;
        for (int idx = l; idx < 120; idx += 16) {
            int p, q; find_pq(idx, p, q);
            pqmap[npair++] = p | (q << 8) | (idx << 16);
        }
        for (int it = 0; it < npair; it++) {
            int pk = pqmap[it];
            int p = pk & 255, q = (pk >> 8) & 255, idx = pk >> 16;
            float re = 0.f, im = 0.f;
#pragma unroll
            for (int k = 0; k < 16; k++) {
                float zk = (k < 8) ? 1.f : -1.f;
                float2 ap = sh_st[g][p][k];
                float2 aq = sh_st[g][q][k];
                re += zk * (ap.x * aq.x + ap.y * aq.y);
                im += zk * (ap.y * aq.x - ap.x * aq.y);
            }
            sh_f[g][16 + idx]  = re;
            sh_f[g][136 + idx] = im;
        }
        __syncthreads();

        // coalesced float4 block write, tf32-rounded
        int j0 = (blockIdx.x - F_BLOCKS) * 8;
#pragma unroll
        for (int it = 0; it < 4; it++) {
            int flat = it * 128 + tid;          // float4 index in [0,512)
            int jl = flat >> 6, t4 = flat & 63; // 64 float4 per row
            const float* s = &sh_f[jl][t4 * 4];
            float4 o = make_float4(to_tf32(s[0]), to_tf32(s[1]),
                                   to_tf32(s[2]), to_tf32(s[3]));
            *(float4*)&g_G[(size_t)(j0 + jl) * FDIM + t4 * 4] = o;
        }
    }
}

// ---- tf32 tensor-core NT GEMM: C[i][j] = | sum_t F[i][t] G[j][t] | ----------
// block tile 128x64, 256 threads (8 warps: 4 m x 2 n), warp tile 32x32,
// mma.m16n8k8 tf32: per warp 2 m-tiles x 4 n-tiles per k8 step. BK=32.

#define BM 128
#define BN 64
#define BK 32
#define APAD 36   // padded k-stride: float4-aligned, conflict-reducing

__global__ __launch_bounds__(256) void gemm_tf32_abs(float* __restrict__ C) {
    __shared__ float As[BM][APAD];
    __shared__ float Bs[BN][APAD];

    int tid = threadIdx.x;
    int warp = tid >> 5, lane = tid & 31;
    int wm = warp >> 1;          // 0..3
    int wn = warp & 1;           // 0..1
    int grp = lane >> 2;         // 0..7
    int tig = lane & 3;          // 0..3

    int i0 = blockIdx.y * BM;
    int j0 = blockIdx.x * BN;

    float acc[2][4][4];
#pragma unroll
    for (int mt = 0; mt < 2; mt++)
#pragma unroll
        for (int nt = 0; nt < 4; nt++)
#pragma unroll
            for (int r = 0; r < 4; r++) acc[mt][nt][r] = 0.f;

    for (int kt = 0; kt < FDIM; kt += BK) {
        // A: 128x32 floats = 1024 float4, 4 per thread
#pragma unroll
        for (int it = 0; it < 4; it++) {
            int v = it * 256 + tid;
            int row = v >> 3, seg = v & 7;
            float4 f = *(const float4*)&g_F[(size_t)(i0 + row) * FDIM + kt + seg * 4];
            *(float4*)&As[row][seg * 4] = f;
        }
        // B: 64x32 floats = 512 float4, 2 per thread
#pragma unroll
        for (int it = 0; it < 2; it++) {
            int v = it * 256 + tid;
            int row = v >> 3, seg = v & 7;
            float4 f = *(const float4*)&g_G[(size_t)(j0 + row) * FDIM + kt + seg * 4];
            *(float4*)&Bs[row][seg * 4] = f;
        }
        __syncthreads();

#pragma unroll
        for (int k8 = 0; k8 < 4; k8++) {
            int k0 = k8 * 8;
            uint32_t afr[2][4], bfr[4][2];
#pragma unroll
            for (int mt = 0; mt < 2; mt++) {
                int r = wm * 32 + mt * 16 + grp;
                afr[mt][0] = __float_as_uint(As[r][k0 + tig]);
                afr[mt][1] = __float_as_uint(As[r + 8][k0 + tig]);
                afr[mt][2] = __float_as_uint(As[r][k0 + tig + 4]);
                afr[mt][3] = __float_as_uint(As[r + 8][k0 + tig + 4]);
            }
#pragma unroll
            for (int nt = 0; nt < 4; nt++) {
                int n = wn * 32 + nt * 8 + grp;
                bfr[nt][0] = __float_as_uint(Bs[n][k0 + tig]);
                bfr[nt][1] = __float_as_uint(Bs[n][k0 + tig + 4]);
            }
#pragma unroll
            for (int mt = 0; mt < 2; mt++)
#pragma unroll
                for (int nt = 0; nt < 4; nt++) {
                    asm volatile(
                        "mma.sync.aligned.m16n8k8.row.col.f32.tf32.tf32.f32 "
                        "{%0,%1,%2,%3}, {%4,%5,%6,%7}, {%8,%9}, {%0,%1,%2,%3};"
                        : "+f"(acc[mt][nt][0]), "+f"(acc[mt][nt][1]),
                          "+f"(acc[mt][nt][2]), "+f"(acc[mt][nt][3])
                        : "r"(afr[mt][0]), "r"(afr[mt][1]),
                          "r"(afr[mt][2]), "r"(afr[mt][3]),
                          "r"(bfr[nt][0]), "r"(bfr[nt][1]));
                }
        }
        __syncthreads();
    }

    // epilogue: c0,c1 at (row, 2tig / 2tig+1), c2,c3 at (row+8, same)
#pragma unroll
    for (int mt = 0; mt < 2; mt++) {
        int row = i0 + wm * 32 + mt * 16 + grp;
#pragma unroll
        for (int nt = 0; nt < 4; nt++) {
            int col = j0 + wn * 32 + nt * 8 + 2 * tig;
            float2 o0 = make_float2(fabsf(acc[mt][nt][0]), fabsf(acc[mt][nt][1]));
            float2 o1 = make_float2(fabsf(acc[mt][nt][2]), fabsf(acc[mt][nt][3]));
            *(float2*)&C[(size_t)row * NROWS + col] = o0;
            *(float2*)&C[(size_t)(row + 8) * NROWS + col] = o1;
        }
    }
}

// ---------------------------------------------------------------------------
extern "C" void kernel_launch(void* const* d_in, const int* in_sizes, int n_in,
                              void* d_out, int out_size) {
    const float* a = (const float*)d_in[0];       // [1024,4]
    const float* b = (const float*)d_in[1];       // [1024,4]
    const float* params = (const float*)d_in[2];  // [2,4,3]
    float* out = (float*)d_out;                   // [1024,1024]

    build_features<<<F_BLOCKS + G_BLOCKS, 128>>>(a, b, params);

    dim3 grid(NROWS / BN, NROWS / BM);   // (16, 8) = 128 blocks
    gemm_tf32_abs<<<grid, 256>>>(out);
}

// round 5
// speedup vs baseline: 4.3405x; 1.2878x over previous
#include <cuda_runtime.h>
#include <math.h>
#include <stdint.h>

// ---------------------------------------------------------------------------
// QuantumKernelMethod: 4 qubits, 2 layers.
// z(i,j) = | u_i^H M_j u_i |,  u_i = A(a_i)|0>,  M_j = A(b_j) Z0 A(b_j)^H.
// Reduced to real NT-GEMM over 256-dim Hermitian feature vectors (tf32 MMA):
//   C = | F [1024x256] * G^T [256x1024] |
// ---------------------------------------------------------------------------

#define NROWS 1024
#define FDIM 256

__device__ float g_F[NROWS * FDIM];   // row features [i][t], tf32-rounded
__device__ float g_G[NROWS * FDIM];   // col features [j][t], tf32-rounded

__device__ __forceinline__ float to_tf32(float x) {
    float r;
    asm("cvt.rna.tf32.f32 %0, %1;" : "=f"(r) : "f"(x));
    return r;
}

// ---- gate machinery ---------------------------------------------------------
// state flat idx = b0*8 + b1*4 + b2*2 + b3 ; wire w -> mask 8>>w

__device__ __forceinline__ void gate_ry_real(float2* st, int m, float c, float s) {
#pragma unroll
    for (int idx = 0; idx < 16; idx++) {
        if (!(idx & m)) {
            float2 x0 = st[idx], x1 = st[idx | m];
            st[idx]     = make_float2(c * x0.x - s * x1.x, c * x0.y - s * x1.y);
            st[idx | m] = make_float2(s * x0.x + c * x1.x, s * x0.y + c * x1.y);
        }
    }
}

__device__ __forceinline__ void gate_u2(float2* st, int m,
                                        float2 u00, float2 u01,
                                        float2 u10, float2 u11) {
#pragma unroll
    for (int idx = 0; idx < 16; idx++) {
        if (!(idx & m)) {
            float2 x0 = st[idx], x1 = st[idx | m];
            float2 n0, n1;
            n0.x = u00.x * x0.x - u00.y * x0.y + u01.x * x1.x - u01.y * x1.y;
            n0.y = u00.x * x0.y + u00.y * x0.x + u01.x * x1.y + u01.y * x1.x;
            n1.x = u10.x * x0.x - u10.y * x0.y + u11.x * x1.x - u11.y * x1.y;
            n1.y = u10.x * x0.y + u10.y * x0.x + u11.x * x1.y + u11.y * x1.x;
            st[idx] = n0;
            st[idx | m] = n1;
        }
    }
}

__device__ __forceinline__ void gate_cnot(float2* st, int mc, int mt) {
#pragma unroll
    for (int idx = 0; idx < 16; idx++) {
        if ((idx & mc) && !(idx & mt)) {
            float2 tmp = st[idx];
            st[idx] = st[idx | mt];
            st[idx | mt] = tmp;
        }
    }
}

__device__ __forceinline__ void apply_ansatz_fused(float2* st, const float* vec,
                                                   const float2 (*shU)[4]) {
#pragma unroll
    for (int i = 0; i < 4; i++) {
        float s, c; __sincosf(0.5f * vec[i], &s, &c);
        gate_ry_real(st, 8 >> i, c, s);
    }
#pragma unroll
    for (int l = 0; l < 2; l++) {
#pragma unroll
        for (int i = 0; i < 4; i++) {
            const float2* U = shU[l * 4 + i];
            gate_u2(st, 8 >> i, U[0], U[1], U[2], U[3]);
        }
        gate_cnot(st, 8, 4);
        gate_cnot(st, 4, 2);
        gate_cnot(st, 2, 1);
        gate_cnot(st, 1, 8);
    }
}

// fused U(l,i) = Rz(c) Ry(b) Rx(a); lanes 0..7 compute one each
__device__ __forceinline__ void build_fused_mats(const float* params,
                                                 float2 (*shU)[4], int tid) {
    if (tid < 8) {
        float a = params[tid * 3 + 0], b = params[tid * 3 + 1], c = params[tid * 3 + 2];
        float sa, ca, sb, cb, sc, cc;
        __sincosf(0.5f * a, &sa, &ca);
        __sincosf(0.5f * b, &sb, &cb);
        __sincosf(0.5f * c, &sc, &cc);
        float2 m00 = make_float2(cb * ca,  sb * sa);
        float2 m01 = make_float2(-sb * ca, -cb * sa);
        float2 m10 = make_float2(sb * ca, -cb * sa);
        float2 m11 = make_float2(cb * ca, -sb * sa);
        shU[tid][0] = make_float2(cc * m00.x + sc * m00.y, cc * m00.y - sc * m00.x);
        shU[tid][1] = make_float2(cc * m01.x + sc * m01.y, cc * m01.y - sc * m01.x);
        shU[tid][2] = make_float2(cc * m10.x - sc * m10.y, cc * m10.y + sc * m10.x);
        shU[tid][3] = make_float2(cc * m11.x - sc * m11.y, cc * m11.y + sc * m11.x);
    }
}

// idx in [0,120) -> (p,q), p<q<16, p-major
__device__ __forceinline__ void find_pq(int idx, int& p, int& q) {
    p = 0;
    while (idx >= 15 - p) { idx -= 15 - p; p++; }
    q = p + 1 + idx;
}

// ---- fused precompute: 256 blocks x 128 threads, 8 rows/block, 16 lanes/row -
// blocks [0,128)   : F-mode (rows of a)
// blocks [128,256) : G-mode (rows of b)
#define FG_BLOCKS 256

__global__ __launch_bounds__(128) void build_features(const float* __restrict__ a,
                                                      const float* __restrict__ b,
                                                      const float* __restrict__ params) {
    __shared__ float2 shU[8][4];
    __shared__ float2 sh_st[8][16][17];  // [group][amp p][lane k] (F uses k=0 only)
    __shared__ float  sh_f[8][256];

    int tid = threadIdx.x;
    build_fused_mats(params, shU, tid);
    __syncthreads();

    bool isF = blockIdx.x < 128;
    int g = tid >> 4;          // row-in-block 0..7
    int l = tid & 15;          // lane-in-row 0..15
    int row = (blockIdx.x & 127) * 8 + g;

    const float* src = isF ? a : b;
    float vec[4];
    {
        float4 v = *(const float4*)&src[row * 4];
        vec[0] = v.x; vec[1] = v.y; vec[2] = v.z; vec[3] = v.w;
    }

    // init state: F -> e_0 (all lanes identical); G -> e_l (lane = column)
    int init = isF ? 0 : l;
    float2 st[16];
#pragma unroll
    for (int k = 0; k < 16; k++)
        st[k] = make_float2((k == init) ? 1.f : 0.f, 0.f);

    apply_ansatz_fused(st, vec, shU);

    // precompute this lane's pair list (idx = l, l+16, ..., l+112)
    int pqmap[8];
#pragma unroll
    for (int it = 0; it < 8; it++) {
        int idx = l + 16 * it;
        if (idx < 120) {
            int p, q; find_pq(idx, p, q);
            pqmap[it] = p | (q << 8) | (idx << 16);
        } else pqmap[it] = -1;
    }

    if (isF) {
        // stash u (identical across lanes): lane 0 writes
        if (l == 0) {
#pragma unroll
            for (int k = 0; k < 16; k++) sh_st[g][k][0] = st[k];
        }
        __syncthreads();

        float2 v = sh_st[g][l][0];
        sh_f[g][l] = v.x * v.x + v.y * v.y;           // diag |u_l|^2

#pragma unroll
        for (int it = 0; it < 8; it++) {
            int pk = pqmap[it];
            if (pk < 0) break;
            int p = pk & 255, q = (pk >> 8) & 255, idx = pk >> 16;
            float2 up = sh_st[g][p][0], uq = sh_st[g][q][0];
            sh_f[g][16 + idx]  = 2.f * (up.x * uq.x + up.y * uq.y);  // 2Re(u_p conj u_q)
            sh_f[g][136 + idx] = 2.f * (up.y * uq.x - up.x * uq.y);  // 2Im
        }
    } else {
        // stash column l of A(b_j)
#pragma unroll
        for (int p = 0; p < 16; p++) sh_st[g][p][l] = st[p];
        __syncthreads();

        // diag: M_pp = sum_k z_k |A[p][k]|^2
        {
            float d = 0.f;
#pragma unroll
            for (int k = 0; k < 16; k++) {
                float zk = (k < 8) ? 1.f : -1.f;
                float2 v = sh_st[g][l][k];
                d += zk * (v.x * v.x + v.y * v.y);
            }
            sh_f[g][l] = d;
        }

#pragma unroll
        for (int it = 0; it < 8; it++) {
            int pk = pqmap[it];
            if (pk < 0) break;
            int p = pk & 255, q = (pk >> 8) & 255, idx = pk >> 16;
            float re = 0.f, im = 0.f;
#pragma unroll
            for (int k = 0; k < 16; k++) {
                float zk = (k < 8) ? 1.f : -1.f;
                float2 ap = sh_st[g][p][k];
                float2 aq = sh_st[g][q][k];
                re += zk * (ap.x * aq.x + ap.y * aq.y);
                im += zk * (ap.y * aq.x - ap.x * aq.y);
            }
            sh_f[g][16 + idx]  = re;
            sh_f[g][136 + idx] = im;
        }
    }
    __syncthreads();

    // coalesced float4 write of the 8x256 feature block, tf32-rounded
    float* dst = isF ? g_F : g_G;
    int r0 = (blockIdx.x & 127) * 8;
#pragma unroll
    for (int it = 0; it < 4; it++) {
        int flat = it * 128 + tid;          // float4 index in [0,512)
        int rl = flat >> 6, t4 = flat & 63;
        const float* s = &sh_f[rl][t4 * 4];
        float4 o = make_float4(to_tf32(s[0]), to_tf32(s[1]),
                               to_tf32(s[2]), to_tf32(s[3]));
        *(float4*)&dst[(size_t)(r0 + rl) * FDIM + t4 * 4] = o;
    }
}

// ---- tf32 NT GEMM with cp.async double buffering ----------------------------
// 64x64 tile, 256 threads (8 warps: 2m x 4n, warp tile 32x16), BK=32, 2 stages.
// grid = 16x16 = 256 blocks -> ~2 blocks/SM.

#define BM 64
#define BN 64
#define BK 32
#define KST 36    // padded k-stride

__device__ __forceinline__ void cp_async16(void* smem_dst, const void* gmem_src) {
    uint32_t s = (uint32_t)__cvta_generic_to_shared(smem_dst);
    asm volatile("cp.async.ca.shared.global [%0], [%1], 16;" :: "r"(s), "l"(gmem_src));
}

__global__ __launch_bounds__(256) void gemm_tf32_abs(float* __restrict__ C) {
    __shared__ float As[2][BM][KST];
    __shared__ float Bs[2][BN][KST];

    int tid = threadIdx.x;
    int warp = tid >> 5, lane = tid & 31;
    int wm = warp >> 2;          // 0..1
    int wn = warp & 3;           // 0..3
    int grp = lane >> 2;         // 0..7
    int tig = lane & 3;          // 0..3

    int i0 = blockIdx.y * BM;
    int j0 = blockIdx.x * BN;

    // per-thread load coords: 512 float4 per matrix per stage, 2 per thread
    int lrow0 = tid >> 2, lseg0 = (tid & 3) * 2;          // variant A: 2 consecutive segs
    // use flat scheme: v = it*256+tid -> row=v>>3, seg=v&7
    float acc[2][2][4];
#pragma unroll
    for (int mt = 0; mt < 2; mt++)
#pragma unroll
        for (int nt = 0; nt < 2; nt++)
#pragma unroll
            for (int r = 0; r < 4; r++) acc[mt][nt][r] = 0.f;
    (void)lrow0; (void)lseg0;

#define LOAD_STAGE(stg, kt_)                                                     \
    do {                                                                          \
        _Pragma("unroll")                                                         \
        for (int it = 0; it < 2; it++) {                                          \
            int v = it * 256 + tid;                                               \
            int row = v >> 3, seg = v & 7;                                        \
            cp_async16(&As[stg][row][seg * 4],                                    \
                       &g_F[(size_t)(i0 + row) * FDIM + (kt_) + seg * 4]);        \
            cp_async16(&Bs[stg][row][seg * 4],                                    \
                       &g_G[(size_t)(j0 + row) * FDIM + (kt_) + seg * 4]);        \
        }                                                                         \
        asm volatile("cp.async.commit_group;");                                   \
    } while (0)

    LOAD_STAGE(0, 0);

#pragma unroll
    for (int kt = 0; kt < FDIM / BK; kt++) {
        int stg = kt & 1;
        if (kt + 1 < FDIM / BK) {
            LOAD_STAGE((kt + 1) & 1, (kt + 1) * BK);
            asm volatile("cp.async.wait_group 1;");
        } else {
            asm volatile("cp.async.wait_group 0;");
        }
        __syncthreads();

#pragma unroll
        for (int k8 = 0; k8 < BK / 8; k8++) {
            int k0 = k8 * 8;
            uint32_t afr[2][4], bfr[2][2];
#pragma unroll
            for (int mt = 0; mt < 2; mt++) {
                int r = wm * 32 + mt * 16 + grp;
                afr[mt][0] = __float_as_uint(As[stg][r][k0 + tig]);
                afr[mt][1] = __float_as_uint(As[stg][r + 8][k0 + tig]);
                afr[mt][2] = __float_as_uint(As[stg][r][k0 + tig + 4]);
                afr[mt][3] = __float_as_uint(As[stg][r + 8][k0 + tig + 4]);
            }
#pragma unroll
            for (int nt = 0; nt < 2; nt++) {
                int n = wn * 16 + nt * 8 + grp;
                bfr[nt][0] = __float_as_uint(Bs[stg][n][k0 + tig]);
                bfr[nt][1] = __float_as_uint(Bs[stg][n][k0 + tig + 4]);
            }
#pragma unroll
            for (int mt = 0; mt < 2; mt++)
#pragma unroll
                for (int nt = 0; nt < 2; nt++) {
                    asm volatile(
                        "mma.sync.aligned.m16n8k8.row.col.f32.tf32.tf32.f32 "
                        "{%0,%1,%2,%3}, {%4,%5,%6,%7}, {%8,%9}, {%0,%1,%2,%3};"
                        : "+f"(acc[mt][nt][0]), "+f"(acc[mt][nt][1]),
                          "+f"(acc[mt][nt][2]), "+f"(acc[mt][nt][3])
                        : "r"(afr[mt][0]), "r"(afr[mt][1]),
                          "r"(afr[mt][2]), "r"(afr[mt][3]),
                          "r"(bfr[nt][0]), "r"(bfr[nt][1]));
                }
        }
        __syncthreads();
    }

    // epilogue
#pragma unroll
    for (int mt = 0; mt < 2; mt++) {
        int rowg = i0 + wm * 32 + mt * 16 + grp;
#pragma unroll
        for (int nt = 0; nt < 2; nt++) {
            int col = j0 + wn * 16 + nt * 8 + 2 * tig;
            float2 o0 = make_float2(fabsf(acc[mt][nt][0]), fabsf(acc[mt][nt][1]));
            float2 o1 = make_float2(fabsf(acc[mt][nt][2]), fabsf(acc[mt][nt][3]));
            *(float2*)&C[(size_t)rowg * NROWS + col] = o0;
            *(float2*)&C[(size_t)(rowg + 8) * NROWS + col] = o1;
        }
    }
}

// ---------------------------------------------------------------------------
extern "C" void kernel_launch(void* const* d_in, const int* in_sizes, int n_in,
                              void* d_out, int out_size) {
    const float* a = (const float*)d_in[0];       // [1024,4]
    const float* b = (const float*)d_in[1];       // [1024,4]
    const float* params = (const float*)d_in[2];  // [2,4,3]
    float* out = (float*)d_out;                   // [1024,1024]

    build_features<<<FG_BLOCKS, 128>>>(a, b, params);

    dim3 grid(NROWS / BN, NROWS / BM);   // (16, 16) = 256 blocks
    gemm_tf32_abs<<<grid, 256>>>(out);
}

// round 6
// speedup vs baseline: 4.4653x; 1.0288x over previous
#include <cuda_runtime.h>
#include <math.h>
#include <stdint.h>

// ---------------------------------------------------------------------------
// QuantumKernelMethod: 4 qubits, 2 layers.
// z(i,j) = | u_i^H M_j u_i |,  u_i = A(a_i)|0>,  M_j = A(b_j) Z0 A(b_j)^H.
// Projector identity: M = I - 2 B B^H with B = A[:, 8:16]  (Z0 = I - 2 P1).
// Reduced to real NT-GEMM over 256-dim Hermitian feature vectors (tf32 MMA):
//   C = | F [1024x256] * G^T [256x1024] |
// ---------------------------------------------------------------------------

#define NROWS 1024
#define FDIM 256

__device__ float g_F[NROWS * FDIM];
__device__ float g_G[NROWS * FDIM];

__device__ __forceinline__ float to_tf32(float x) {
    float r;
    asm("cvt.rna.tf32.f32 %0, %1;" : "=f"(r) : "f"(x));
    return r;
}

// ---- gate machinery ---------------------------------------------------------
__device__ __forceinline__ void gate_ry_real(float2* st, int m, float c, float s) {
#pragma unroll
    for (int idx = 0; idx < 16; idx++) {
        if (!(idx & m)) {
            float2 x0 = st[idx], x1 = st[idx | m];
            st[idx]     = make_float2(c * x0.x - s * x1.x, c * x0.y - s * x1.y);
            st[idx | m] = make_float2(s * x0.x + c * x1.x, s * x0.y + c * x1.y);
        }
    }
}

__device__ __forceinline__ void gate_u2(float2* st, int m,
                                        float2 u00, float2 u01,
                                        float2 u10, float2 u11) {
#pragma unroll
    for (int idx = 0; idx < 16; idx++) {
        if (!(idx & m)) {
            float2 x0 = st[idx], x1 = st[idx | m];
            float2 n0, n1;
            n0.x = u00.x * x0.x - u00.y * x0.y + u01.x * x1.x - u01.y * x1.y;
            n0.y = u00.x * x0.y + u00.y * x0.x + u01.x * x1.y + u01.y * x1.x;
            n1.x = u10.x * x0.x - u10.y * x0.y + u11.x * x1.x - u11.y * x1.y;
            n1.y = u10.x * x0.y + u10.y * x0.x + u11.x * x1.y + u11.y * x1.x;
            st[idx] = n0;
            st[idx | m] = n1;
        }
    }
}

__device__ __forceinline__ void gate_cnot(float2* st, int mc, int mt) {
#pragma unroll
    for (int idx = 0; idx < 16; idx++) {
        if ((idx & mc) && !(idx & mt)) {
            float2 tmp = st[idx];
            st[idx] = st[idx | mt];
            st[idx | mt] = tmp;
        }
    }
}

__device__ __forceinline__ void apply_ansatz_fused(float2* st, const float* vec,
                                                   const float2 (*shU)[4]) {
#pragma unroll
    for (int i = 0; i < 4; i++) {
        float s, c; __sincosf(0.5f * vec[i], &s, &c);
        gate_ry_real(st, 8 >> i, c, s);
    }
#pragma unroll
    for (int l = 0; l < 2; l++) {
#pragma unroll
        for (int i = 0; i < 4; i++) {
            const float2* U = shU[l * 4 + i];
            gate_u2(st, 8 >> i, U[0], U[1], U[2], U[3]);
        }
        gate_cnot(st, 8, 4);
        gate_cnot(st, 4, 2);
        gate_cnot(st, 2, 1);
        gate_cnot(st, 1, 8);
    }
}

__device__ __forceinline__ void build_fused_mats(const float* params,
                                                 float2 (*shU)[4], int tid) {
    if (tid < 8) {
        float a = params[tid * 3 + 0], b = params[tid * 3 + 1], c = params[tid * 3 + 2];
        float sa, ca, sb, cb, sc, cc;
        __sincosf(0.5f * a, &sa, &ca);
        __sincosf(0.5f * b, &sb, &cb);
        __sincosf(0.5f * c, &sc, &cc);
        float2 m00 = make_float2(cb * ca,  sb * sa);
        float2 m01 = make_float2(-sb * ca, -cb * sa);
        float2 m10 = make_float2(sb * ca, -cb * sa);
        float2 m11 = make_float2(cb * ca, -sb * sa);
        shU[tid][0] = make_float2(cc * m00.x + sc * m00.y, cc * m00.y - sc * m00.x);
        shU[tid][1] = make_float2(cc * m01.x + sc * m01.y, cc * m01.y - sc * m01.x);
        shU[tid][2] = make_float2(cc * m10.x - sc * m10.y, cc * m10.y + sc * m10.x);
        shU[tid][3] = make_float2(cc * m11.x - sc * m11.y, cc * m11.y + sc * m11.x);
    }
}

// idx in [0,120) -> (p,q), p<q<16: sqrt seed + exact correction
__device__ __forceinline__ void pq_from_idx(int idx, int& p, int& q) {
    float d = 240.25f - 2.f * (float)idx;
    p = (int)(15.5f - sqrtf(d));
    if (p < 0) p = 0;
    int rem = idx - (15 * p - ((p * (p - 1)) >> 1));
    while (rem < 0) { p--; rem = idx - (15 * p - ((p * (p - 1)) >> 1)); }
    while (rem >= 15 - p) { rem -= 15 - p; p++; }
    q = p + 1 + rem;
}

// ---- fused precompute: 128 blocks x 128 threads -----------------------------
// 16 rows/block, 8 lanes/row.  blocks [0,64): F (rows of a); [64,128): G (b).
#define FG_BLOCKS 128

__global__ __launch_bounds__(128) void build_features(const float* __restrict__ a,
                                                      const float* __restrict__ b,
                                                      const float* __restrict__ params) {
    __shared__ float2 shU[8][4];
    __shared__ float2 sh_st[16][16][9];   // [group][amp p][lane k]; F uses k=0
    __shared__ float  sh_f[16][256];

    int tid = threadIdx.x;
    build_fused_mats(params, shU, tid);
    __syncthreads();

    bool isF = blockIdx.x < 64;
    int g = tid >> 3;          // row-in-block 0..15
    int l = tid & 7;           // lane-in-row 0..7
    int row = (blockIdx.x & 63) * 16 + g;

    const float* src = isF ? a : b;
    float vec[4];
    {
        float4 v = *(const float4*)&src[row * 4];
        vec[0] = v.x; vec[1] = v.y; vec[2] = v.z; vec[3] = v.w;
    }

    // init state: F -> e_0 (redundant across 8 lanes); G -> e_{8+l} (column 8+l)
    int init = isF ? 0 : (8 + l);
    float2 st[16];
#pragma unroll
    for (int k = 0; k < 16; k++)
        st[k] = make_float2((k == init) ? 1.f : 0.f, 0.f);

    apply_ansatz_fused(st, vec, shU);

    if (isF) {
        if (l == 0) {
#pragma unroll
            for (int k = 0; k < 16; k++) sh_st[g][k][0] = st[k];
        }
    } else {
#pragma unroll
        for (int p = 0; p < 16; p++) sh_st[g][p][l] = st[p];
    }
    __syncthreads();

    if (isF) {
        // diag: |u_p|^2 for p = l, l+8
#pragma unroll
        for (int h = 0; h < 2; h++) {
            int p = l + 8 * h;
            float2 v = sh_st[g][p][0];
            sh_f[g][p] = v.x * v.x + v.y * v.y;
        }
        // off-diag: idx = l, l+8, ..., l+112  (15 per lane)
#pragma unroll
        for (int it = 0; it < 15; it++) {
            int idx = l + 8 * it;
            int p, q; pq_from_idx(idx, p, q);
            float2 up = sh_st[g][p][0], uq = sh_st[g][q][0];
            sh_f[g][16 + idx]  = 2.f * (up.x * uq.x + up.y * uq.y);  // 2Re(u_p conj u_q)
            sh_f[g][136 + idx] = 2.f * (up.y * uq.x - up.x * uq.y);  // 2Im
        }
    } else {
        // M = I - 2 B B^H, B = A[:,8:16] (stashed 8 columns)
#pragma unroll
        for (int h = 0; h < 2; h++) {
            int p = l + 8 * h;
            float s2 = 0.f;
#pragma unroll
            for (int k = 0; k < 8; k++) {
                float2 v = sh_st[g][p][k];
                s2 += v.x * v.x + v.y * v.y;
            }
            sh_f[g][p] = 1.f - 2.f * s2;
        }
#pragma unroll
        for (int it = 0; it < 15; it++) {
            int idx = l + 8 * it;
            int p, q; pq_from_idx(idx, p, q);
            float re = 0.f, im = 0.f;
#pragma unroll
            for (int k = 0; k < 8; k++) {
                float2 ap = sh_st[g][p][k];
                float2 aq = sh_st[g][q][k];
                re += ap.x * aq.x + ap.y * aq.y;   // Re(A_pk conj A_qk)
                im += ap.y * aq.x - ap.x * aq.y;   // Im(A_pk conj A_qk)
            }
            sh_f[g][16 + idx]  = -2.f * re;
            sh_f[g][136 + idx] = -2.f * im;
        }
    }
    __syncthreads();

    // coalesced float4 write: 16 rows x 256 = 1024 float4, 8 per thread
    float* dst = isF ? g_F : g_G;
    int r0 = (blockIdx.x & 63) * 16;
#pragma unroll
    for (int it = 0; it < 8; it++) {
        int flat = it * 128 + tid;
        int rl = flat >> 6, t4 = flat & 63;
        const float* s = &sh_f[rl][t4 * 4];
        float4 o = make_float4(to_tf32(s[0]), to_tf32(s[1]),
                               to_tf32(s[2]), to_tf32(s[3]));
        *(float4*)&dst[(size_t)(r0 + rl) * FDIM + t4 * 4] = o;
    }
}

// ---- tf32 NT GEMM: 3-stage cp.async + register frag double buffer -----------
// 64x64 tile, 256 threads (8 warps: 2m x 4n, warp tile 32x16), BK=32.

#define BM 64
#define BN 64
#define BK 32
#define KST 36
#define STAGES 3
#define GEMM_SMEM (STAGES * BM * KST * 4 * 2)

__device__ __forceinline__ void cp_async16(void* smem_dst, const void* gmem_src) {
    uint32_t s = (uint32_t)__cvta_generic_to_shared(smem_dst);
    asm volatile("cp.async.ca.shared.global [%0], [%1], 16;" :: "r"(s), "l"(gmem_src));
}

__global__ __launch_bounds__(256) void gemm_tf32_abs(float* __restrict__ C) {
    extern __shared__ float smem_dyn[];
    float (*As)[BM][KST] = (float(*)[BM][KST])smem_dyn;
    float (*Bs)[BM][KST] = (float(*)[BM][KST])(smem_dyn + STAGES * BM * KST);

    int tid = threadIdx.x;
    int warp = tid >> 5, lane = tid & 31;
    int wm = warp >> 2;          // 0..1
    int wn = warp & 3;           // 0..3
    int grp = lane >> 2;         // 0..7
    int tig = lane & 3;          // 0..3

    int i0 = blockIdx.y * BM;
    int j0 = blockIdx.x * BN;

    float acc[2][2][4];
#pragma unroll
    for (int mt = 0; mt < 2; mt++)
#pragma unroll
        for (int nt = 0; nt < 2; nt++)
#pragma unroll
            for (int r = 0; r < 4; r++) acc[mt][nt][r] = 0.f;

#define LOAD_STAGE(stg, kt_)                                                     \
    do {                                                                          \
        _Pragma("unroll")                                                         \
        for (int it = 0; it < 2; it++) {                                          \
            int v = it * 256 + tid;                                               \
            int lrow = v >> 3, lseg = v & 7;                                      \
            cp_async16(&As[stg][lrow][lseg * 4],                                  \
                       &g_F[(size_t)(i0 + lrow) * FDIM + (kt_) + lseg * 4]);      \
            cp_async16(&Bs[stg][lrow][lseg * 4],                                  \
                       &g_G[(size_t)(j0 + lrow) * FDIM + (kt_) + lseg * 4]);      \
        }                                                                         \
        asm volatile("cp.async.commit_group;");                                   \
    } while (0)

#define LDFRAG(buf, stg, k8_)                                                    \
    do {                                                                          \
        int k0 = (k8_) * 8;                                                       \
        _Pragma("unroll")                                                         \
        for (int mt = 0; mt < 2; mt++) {                                          \
            int r = wm * 32 + mt * 16 + grp;                                      \
            afr[buf][mt][0] = __float_as_uint(As[stg][r][k0 + tig]);              \
            afr[buf][mt][1] = __float_as_uint(As[stg][r + 8][k0 + tig]);          \
            afr[buf][mt][2] = __float_as_uint(As[stg][r][k0 + tig + 4]);          \
            afr[buf][mt][3] = __float_as_uint(As[stg][r + 8][k0 + tig + 4]);      \
        }                                                                         \
        _Pragma("unroll")                                                         \
        for (int nt = 0; nt < 2; nt++) {                                          \
            int n = wn * 16 + nt * 8 + grp;                                       \
            bfr[buf][nt][0] = __float_as_uint(Bs[stg][n][k0 + tig]);              \
            bfr[buf][nt][1] = __float_as_uint(Bs[stg][n][k0 + tig + 4]);          \
        }                                                                         \
    } while (0)

#define DO_MMAS(buf)                                                             \
    do {                                                                          \
        _Pragma("unroll")                                                         \
        for (int mt = 0; mt < 2; mt++)                                            \
            _Pragma("unroll")                                                     \
            for (int nt = 0; nt < 2; nt++) {                                      \
                asm volatile(                                                     \
                    "mma.sync.aligned.m16n8k8.row.col.f32.tf32.tf32.f32 "         \
                    "{%0,%1,%2,%3}, {%4,%5,%6,%7}, {%8,%9}, {%0,%1,%2,%3};"       \
                    : "+f"(acc[mt][nt][0]), "+f"(acc[mt][nt][1]),                 \
                      "+f"(acc[mt][nt][2]), "+f"(acc[mt][nt][3])                  \
                    : "r"(afr[buf][mt][0]), "r"(afr[buf][mt][1]),                 \
                      "r"(afr[buf][mt][2]), "r"(afr[buf][mt][3]),                 \
                      "r"(bfr[buf][nt][0]), "r"(bfr[buf][nt][1]));                \
            }                                                                     \
    } while (0)

    LOAD_STAGE(0, 0);
    LOAD_STAGE(1, BK);

#pragma unroll
    for (int kt = 0; kt < FDIM / BK; kt++) {
        int stg = kt % STAGES;
        if (kt < FDIM / BK - 1)
            asm volatile("cp.async.wait_group 1;");
        else
            asm volatile("cp.async.wait_group 0;");
        __syncthreads();

        if (kt + 2 < FDIM / BK)
            LOAD_STAGE((kt + 2) % STAGES, (kt + 2) * BK);

        uint32_t afr[2][2][4], bfr[2][2][2];
        LDFRAG(0, stg, 0);
#pragma unroll
        for (int k8 = 0; k8 < BK / 8; k8++) {
            int cur = k8 & 1;
            if (k8 + 1 < BK / 8) LDFRAG(cur ^ 1, stg, k8 + 1);
            DO_MMAS(cur);
        }
    }

    // epilogue
#pragma unroll
    for (int mt = 0; mt < 2; mt++) {
        int rowg = i0 + wm * 32 + mt * 16 + grp;
#pragma unroll
        for (int nt = 0; nt < 2; nt++) {
            int col = j0 + wn * 16 + nt * 8 + 2 * tig;
            float2 o0 = make_float2(fabsf(acc[mt][nt][0]), fabsf(acc[mt][nt][1]));
            float2 o1 = make_float2(fabsf(acc[mt][nt][2]), fabsf(acc[mt][nt][3]));
            *(float2*)&C[(size_t)rowg * NROWS + col] = o0;
            *(float2*)&C[(size_t)(rowg + 8) * NROWS + col] = o1;
        }
    }
}

// ---------------------------------------------------------------------------
extern "C" void kernel_launch(void* const* d_in, const int* in_sizes, int n_in,
                              void* d_out, int out_size) {
    const float* a = (const float*)d_in[0];       // [1024,4]
    const float* b = (const float*)d_in[1];       // [1024,4]
    const float* params = (const float*)d_in[2];  // [2,4,3]
    float* out = (float*)d_out;                   // [1024,1024]

    cudaFuncSetAttribute(gemm_tf32_abs,
                         cudaFuncAttributeMaxDynamicSharedMemorySize, GEMM_SMEM);

    build_features<<<FG_BLOCKS, 128>>>(a, b, params);

    dim3 grid(NROWS / BN, NROWS / BM);   // (16, 16) = 256 blocks
    gemm_tf32_abs<<<grid, 256, GEMM_SMEM>>>(out);
}

// round 7
// speedup vs baseline: 4.8600x; 1.0884x over previous
#include <cuda_runtime.h>
#include <cuda_fp16.h>
#include <math.h>
#include <stdint.h>

// ---------------------------------------------------------------------------
// QuantumKernelMethod: 4 qubits, 2 layers.
// z(i,j) = | u_i^H M_j u_i |,  u_i = A(a_i)|0>,  M_j = A(b_j) Z0 A(b_j)^H.
// Projector identity: M = I - 2 B B^H with B = A[:, 8:16].
// Reduced to real NT-GEMM over 256-dim Hermitian feature vectors (fp16 MMA,
// fp32 accumulate; fp16 mantissa == tf32 mantissa for O(1) features):
//   C = | F [1024x256] * G^T [256x1024] |
// ---------------------------------------------------------------------------

#define NROWS 1024
#define FDIM 256

__device__ __align__(16) __half g_F[NROWS * FDIM];
__device__ __align__(16) __half g_G[NROWS * FDIM];

// ---- gate machinery ---------------------------------------------------------
__device__ __forceinline__ void gate_ry_real(float2* st, int m, float c, float s) {
#pragma unroll
    for (int idx = 0; idx < 16; idx++) {
        if (!(idx & m)) {
            float2 x0 = st[idx], x1 = st[idx | m];
            st[idx]     = make_float2(c * x0.x - s * x1.x, c * x0.y - s * x1.y);
            st[idx | m] = make_float2(s * x0.x + c * x1.x, s * x0.y + c * x1.y);
        }
    }
}

__device__ __forceinline__ void gate_u2(float2* st, int m,
                                        float2 u00, float2 u01,
                                        float2 u10, float2 u11) {
#pragma unroll
    for (int idx = 0; idx < 16; idx++) {
        if (!(idx & m)) {
            float2 x0 = st[idx], x1 = st[idx | m];
            float2 n0, n1;
            n0.x = u00.x * x0.x - u00.y * x0.y + u01.x * x1.x - u01.y * x1.y;
            n0.y = u00.x * x0.y + u00.y * x0.x + u01.x * x1.y + u01.y * x1.x;
            n1.x = u10.x * x0.x - u10.y * x0.y + u11.x * x1.x - u11.y * x1.y;
            n1.y = u10.x * x0.y + u10.y * x0.x + u11.x * x1.y + u11.y * x1.x;
            st[idx] = n0;
            st[idx | m] = n1;
        }
    }
}

__device__ __forceinline__ void gate_cnot(float2* st, int mc, int mt) {
#pragma unroll
    for (int idx = 0; idx < 16; idx++) {
        if ((idx & mc) && !(idx & mt)) {
            float2 tmp = st[idx];
            st[idx] = st[idx | mt];
            st[idx | mt] = tmp;
        }
    }
}

__device__ __forceinline__ void apply_ansatz_fused(float2* st, const float* vec,
                                                   const float2 (*shU)[4]) {
#pragma unroll
    for (int i = 0; i < 4; i++) {
        float s, c; __sincosf(0.5f * vec[i], &s, &c);
        gate_ry_real(st, 8 >> i, c, s);
    }
#pragma unroll
    for (int l = 0; l < 2; l++) {
#pragma unroll
        for (int i = 0; i < 4; i++) {
            const float2* U = shU[l * 4 + i];
            gate_u2(st, 8 >> i, U[0], U[1], U[2], U[3]);
        }
        gate_cnot(st, 8, 4);
        gate_cnot(st, 4, 2);
        gate_cnot(st, 2, 1);
        gate_cnot(st, 1, 8);
    }
}

__device__ __forceinline__ void build_fused_mats(const float* params,
                                                 float2 (*shU)[4], int tid) {
    if (tid < 8) {
        float a = params[tid * 3 + 0], b = params[tid * 3 + 1], c = params[tid * 3 + 2];
        float sa, ca, sb, cb, sc, cc;
        __sincosf(0.5f * a, &sa, &ca);
        __sincosf(0.5f * b, &sb, &cb);
        __sincosf(0.5f * c, &sc, &cc);
        float2 m00 = make_float2(cb * ca,  sb * sa);
        float2 m01 = make_float2(-sb * ca, -cb * sa);
        float2 m10 = make_float2(sb * ca, -cb * sa);
        float2 m11 = make_float2(cb * ca, -sb * sa);
        shU[tid][0] = make_float2(cc * m00.x + sc * m00.y, cc * m00.y - sc * m00.x);
        shU[tid][1] = make_float2(cc * m01.x + sc * m01.y, cc * m01.y - sc * m01.x);
        shU[tid][2] = make_float2(cc * m10.x - sc * m10.y, cc * m10.y + sc * m10.x);
        shU[tid][3] = make_float2(cc * m11.x - sc * m11.y, cc * m11.y + sc * m11.x);
    }
}

// idx in [0,120) -> (p,q), p<q<16: sqrt seed + exact correction
__device__ __forceinline__ void pq_from_idx(int idx, int& p, int& q) {
    float d = 240.25f - 2.f * (float)idx;
    p = (int)(15.5f - sqrtf(d));
    if (p < 0) p = 0;
    int rem = idx - (15 * p - ((p * (p - 1)) >> 1));
    while (rem < 0) { p--; rem = idx - (15 * p - ((p * (p - 1)) >> 1)); }
    while (rem >= 15 - p) { rem -= 15 - p; p++; }
    q = p + 1 + rem;
}

// ---- fused precompute: 256 blocks x 64 threads ------------------------------
// 8 rows/block, 8 lanes/row.  blocks [0,128): F (rows of a); [128,256): G (b).
#define FG_BLOCKS 256

__global__ __launch_bounds__(64) void build_features(const float* __restrict__ a,
                                                     const float* __restrict__ b,
                                                     const float* __restrict__ params) {
    __shared__ float2 shU[8][4];
    __shared__ float2 sh_st[8][16][9];    // [group][amp p][lane k]; F uses k=0
    __shared__ float  sh_f[8][256];

    int tid = threadIdx.x;
    build_fused_mats(params, shU, tid);
    __syncthreads();

    bool isF = blockIdx.x < 128;
    int g = tid >> 3;          // row-in-block 0..7
    int l = tid & 7;           // lane-in-row 0..7
    int row = (blockIdx.x & 127) * 8 + g;

    const float* src = isF ? a : b;
    float vec[4];
    {
        float4 v = *(const float4*)&src[row * 4];
        vec[0] = v.x; vec[1] = v.y; vec[2] = v.z; vec[3] = v.w;
    }

    // init state: F -> e_0 (redundant across 8 lanes); G -> e_{8+l}
    int init = isF ? 0 : (8 + l);
    float2 st[16];
#pragma unroll
    for (int k = 0; k < 16; k++)
        st[k] = make_float2((k == init) ? 1.f : 0.f, 0.f);

    apply_ansatz_fused(st, vec, shU);

    if (isF) {
        if (l == 0) {
#pragma unroll
            for (int k = 0; k < 16; k++) sh_st[g][k][0] = st[k];
        }
    } else {
#pragma unroll
        for (int p = 0; p < 16; p++) sh_st[g][p][l] = st[p];
    }
    __syncthreads();

    if (isF) {
#pragma unroll
        for (int h = 0; h < 2; h++) {
            int p = l + 8 * h;
            float2 v = sh_st[g][p][0];
            sh_f[g][p] = v.x * v.x + v.y * v.y;
        }
#pragma unroll
        for (int it = 0; it < 15; it++) {
            int idx = l + 8 * it;
            int p, q; pq_from_idx(idx, p, q);
            float2 up = sh_st[g][p][0], uq = sh_st[g][q][0];
            sh_f[g][16 + idx]  = 2.f * (up.x * uq.x + up.y * uq.y);
            sh_f[g][136 + idx] = 2.f * (up.y * uq.x - up.x * uq.y);
        }
    } else {
        // M = I - 2 B B^H, B = A[:,8:16]
#pragma unroll
        for (int h = 0; h < 2; h++) {
            int p = l + 8 * h;
            float s2 = 0.f;
#pragma unroll
            for (int k = 0; k < 8; k++) {
                float2 v = sh_st[g][p][k];
                s2 += v.x * v.x + v.y * v.y;
            }
            sh_f[g][p] = 1.f - 2.f * s2;
        }
#pragma unroll
        for (int it = 0; it < 15; it++) {
            int idx = l + 8 * it;
            int p, q; pq_from_idx(idx, p, q);
            float re = 0.f, im = 0.f;
#pragma unroll
            for (int k = 0; k < 8; k++) {
                float2 ap = sh_st[g][p][k];
                float2 aq = sh_st[g][q][k];
                re += ap.x * aq.x + ap.y * aq.y;
                im += ap.y * aq.x - ap.x * aq.y;
            }
            sh_f[g][16 + idx]  = -2.f * re;
            sh_f[g][136 + idx] = -2.f * im;
        }
    }
    __syncthreads();

    // coalesced half2 write: 8 rows x 128 half2 = 1024 half2, 16 per thread
    __half2* dst = (__half2*)(isF ? g_F : g_G);
    int r0 = (blockIdx.x & 127) * 8;
#pragma unroll
    for (int it = 0; it < 16; it++) {
        int flat = it * 64 + tid;
        int rl = flat >> 7, t2 = flat & 127;
        __half2 o = __floats2half2_rn(sh_f[rl][2 * t2], sh_f[rl][2 * t2 + 1]);
        dst[(size_t)(r0 + rl) * (FDIM / 2) + t2] = o;
    }
}

// ---- fp16 NT GEMM: 3-stage cp.async, m16n8k16, fp32 accumulate --------------
// 64x64 tile, 256 threads (8 warps: 2m x 4n, warp tile 32x16), BK=32 halves.

#define BM 64
#define BN 64
#define BK 32
#define KSTH 40   // padded row stride in halves: banks r*20+{0..3} all distinct
#define STAGES 3

__device__ __forceinline__ void cp_async16(void* smem_dst, const void* gmem_src) {
    uint32_t s = (uint32_t)__cvta_generic_to_shared(smem_dst);
    asm volatile("cp.async.ca.shared.global [%0], [%1], 16;" :: "r"(s), "l"(gmem_src));
}

__global__ __launch_bounds__(256) void gemm_f16_abs(float* __restrict__ C) {
    __shared__ __align__(16) __half As[STAGES][BM][KSTH];
    __shared__ __align__(16) __half Bs[STAGES][BN][KSTH];

    int tid = threadIdx.x;
    int warp = tid >> 5, lane = tid & 31;
    int wm = warp >> 2;          // 0..1
    int wn = warp & 3;           // 0..3
    int grp = lane >> 2;         // 0..7
    int tig = lane & 3;          // 0..3

    int i0 = blockIdx.y * BM;
    int j0 = blockIdx.x * BN;

    float acc[2][2][4];
#pragma unroll
    for (int mt = 0; mt < 2; mt++)
#pragma unroll
        for (int nt = 0; nt < 2; nt++)
#pragma unroll
            for (int r = 0; r < 4; r++) acc[mt][nt][r] = 0.f;

    // 64 rows x 32 halves = 64 rows x 4 x 16B chunks = 256 chunks per matrix
    int lrow = tid >> 2, lseg = tid & 3;

#define LOAD_STAGE(stg, kt_)                                                     \
    do {                                                                          \
        cp_async16(&As[stg][lrow][lseg * 8],                                      \
                   &g_F[(size_t)(i0 + lrow) * FDIM + (kt_) + lseg * 8]);          \
        cp_async16(&Bs[stg][lrow][lseg * 8],                                      \
                   &g_G[(size_t)(j0 + lrow) * FDIM + (kt_) + lseg * 8]);          \
        asm volatile("cp.async.commit_group;");                                   \
    } while (0)

#define LDFRAG(buf, stg, k16_)                                                   \
    do {                                                                          \
        int k0 = (k16_) * 16 + 2 * tig;                                           \
        _Pragma("unroll")                                                         \
        for (int mt = 0; mt < 2; mt++) {                                          \
            int r = wm * 32 + mt * 16 + grp;                                      \
            afr[buf][mt][0] = *(const uint32_t*)&As[stg][r][k0];                  \
            afr[buf][mt][1] = *(const uint32_t*)&As[stg][r + 8][k0];              \
            afr[buf][mt][2] = *(const uint32_t*)&As[stg][r][k0 + 8];              \
            afr[buf][mt][3] = *(const uint32_t*)&As[stg][r + 8][k0 + 8];          \
        }                                                                         \
        _Pragma("unroll")                                                         \
        for (int nt = 0; nt < 2; nt++) {                                          \
            int n = wn * 16 + nt * 8 + grp;                                       \
            bfr[buf][nt][0] = *(const uint32_t*)&Bs[stg][n][k0];                  \
            bfr[buf][nt][1] = *(const uint32_t*)&Bs[stg][n][k0 + 8];              \
        }                                                                         \
    } while (0)

#define DO_MMAS(buf)                                                             \
    do {                                                                          \
        _Pragma("unroll")                                                         \
        for (int mt = 0; mt < 2; mt++)                                            \
            _Pragma("unroll")                                                     \
            for (int nt = 0; nt < 2; nt++) {                                      \
                asm volatile(                                                     \
                    "mma.sync.aligned.m16n8k16.row.col.f32.f16.f16.f32 "          \
                    "{%0,%1,%2,%3}, {%4,%5,%6,%7}, {%8,%9}, {%0,%1,%2,%3};"       \
                    : "+f"(acc[mt][nt][0]), "+f"(acc[mt][nt][1]),                 \
                      "+f"(acc[mt][nt][2]), "+f"(acc[mt][nt][3])                  \
                    : "r"(afr[buf][mt][0]), "r"(afr[buf][mt][1]),                 \
                      "r"(afr[buf][mt][2]), "r"(afr[buf][mt][3]),                 \
                      "r"(bfr[buf][nt][0]), "r"(bfr[buf][nt][1]));                \
            }                                                                     \
    } while (0)

    LOAD_STAGE(0, 0);
    LOAD_STAGE(1, BK);

#pragma unroll
    for (int kt = 0; kt < FDIM / BK; kt++) {
        int stg = kt % STAGES;
        if (kt < FDIM / BK - 1)
            asm volatile("cp.async.wait_group 1;");
        else
            asm volatile("cp.async.wait_group 0;");
        __syncthreads();

        if (kt + 2 < FDIM / BK)
            LOAD_STAGE((kt + 2) % STAGES, (kt + 2) * BK);

        uint32_t afr[2][2][4], bfr[2][2][2];
        LDFRAG(0, stg, 0);
        // k16 step 0 (prefetch step 1 into buf 1)
        LDFRAG(1, stg, 1);
        DO_MMAS(0);
        DO_MMAS(1);
    }

    // epilogue: c0,c1 -> (grp, 2tig/2tig+1); c2,c3 -> (grp+8, same)
#pragma unroll
    for (int mt = 0; mt < 2; mt++) {
        int rowg = i0 + wm * 32 + mt * 16 + grp;
#pragma unroll
        for (int nt = 0; nt < 2; nt++) {
            int col = j0 + wn * 16 + nt * 8 + 2 * tig;
            float2 o0 = make_float2(fabsf(acc[mt][nt][0]), fabsf(acc[mt][nt][1]));
            float2 o1 = make_float2(fabsf(acc[mt][nt][2]), fabsf(acc[mt][nt][3]));
            *(float2*)&C[(size_t)rowg * NROWS + col] = o0;
            *(float2*)&C[(size_t)(rowg + 8) * NROWS + col] = o1;
        }
    }
}

// ---------------------------------------------------------------------------
extern "C" void kernel_launch(void* const* d_in, const int* in_sizes, int n_in,
                              void* d_out, int out_size) {
    const float* a = (const float*)d_in[0];       // [1024,4]
    const float* b = (const float*)d_in[1];       // [1024,4]
    const float* params = (const float*)d_in[2];  // [2,4,3]
    float* out = (float*)d_out;                   // [1024,1024]

    build_features<<<FG_BLOCKS, 64>>>(a, b, params);

    dim3 grid(NROWS / BN, NROWS / BM);   // (16, 16) = 256 blocks
    gemm_f16_abs<<<grid, 256>>>(out);
}

// round 8
// speedup vs baseline: 5.0750x; 1.0442x over previous
#include <cuda_runtime.h>
#include <cuda_fp16.h>
#include <math.h>
#include <stdint.h>

// ---------------------------------------------------------------------------
// QuantumKernelMethod: 4 qubits, 2 layers.
// z(i,j) = | u_i^H M_j u_i |, u_i = A(a_i)|0>, M_j = A(b_j) Z0 A(b_j)^H.
// A(x) = U_fixed * (tensor_q Ry(x_q)); product-state columns make the
// data-dependent part a real 16-vector. M = I - 2 B B^H, B = A[:,8:16].
// Gram matrix = | F[1024x256] * G^T | via fp16 MMA (fp32 accumulate).
// ---------------------------------------------------------------------------

#define NROWS 1024
#define FDIM 256

__device__ __align__(16) __half g_F[NROWS * FDIM];
__device__ __align__(16) __half g_G[NROWS * FDIM];
__device__ float2 g_U[256];   // U_fixed[p][k], row-major

// ---- gate machinery (used only by the tiny U_fixed kernel) ------------------
__device__ __forceinline__ void gate_u2(float2* st, int m,
                                        float2 u00, float2 u01,
                                        float2 u10, float2 u11) {
#pragma unroll
    for (int idx = 0; idx < 16; idx++) {
        if (!(idx & m)) {
            float2 x0 = st[idx], x1 = st[idx | m];
            float2 n0, n1;
            n0.x = u00.x * x0.x - u00.y * x0.y + u01.x * x1.x - u01.y * x1.y;
            n0.y = u00.x * x0.y + u00.y * x0.x + u01.x * x1.y + u01.y * x1.x;
            n1.x = u10.x * x0.x - u10.y * x0.y + u11.x * x1.x - u11.y * x1.y;
            n1.y = u10.x * x0.y + u10.y * x0.x + u11.x * x1.y + u11.y * x1.x;
            st[idx] = n0;
            st[idx | m] = n1;
        }
    }
}

__device__ __forceinline__ void gate_cnot(float2* st, int mc, int mt) {
#pragma unroll
    for (int idx = 0; idx < 16; idx++) {
        if ((idx & mc) && !(idx & mt)) {
            float2 tmp = st[idx];
            st[idx] = st[idx | mt];
            st[idx | mt] = tmp;
        }
    }
}

__device__ __forceinline__ void build_fused_mats(const float* params,
                                                 float2 (*shU)[4], int tid) {
    if (tid < 8) {
        float a = params[tid * 3 + 0], b = params[tid * 3 + 1], c = params[tid * 3 + 2];
        float sa, ca, sb, cb, sc, cc;
        __sincosf(0.5f * a, &sa, &ca);
        __sincosf(0.5f * b, &sb, &cb);
        __sincosf(0.5f * c, &sc, &cc);
        float2 m00 = make_float2(cb * ca,  sb * sa);
        float2 m01 = make_float2(-sb * ca, -cb * sa);
        float2 m10 = make_float2(sb * ca, -cb * sa);
        float2 m11 = make_float2(cb * ca, -sb * sa);
        shU[tid][0] = make_float2(cc * m00.x + sc * m00.y, cc * m00.y - sc * m00.x);
        shU[tid][1] = make_float2(cc * m01.x + sc * m01.y, cc * m01.y - sc * m01.x);
        shU[tid][2] = make_float2(cc * m10.x - sc * m10.y, cc * m10.y + sc * m10.x);
        shU[tid][3] = make_float2(cc * m11.x - sc * m11.y, cc * m11.y + sc * m11.x);
    }
}

// fixed part of the ansatz (everything after the initial Ry layer)
__device__ __forceinline__ void apply_layers(float2* st, const float2 (*shU)[4]) {
#pragma unroll
    for (int l = 0; l < 2; l++) {
#pragma unroll
        for (int i = 0; i < 4; i++) {
            const float2* U = shU[l * 4 + i];
            gate_u2(st, 8 >> i, U[0], U[1], U[2], U[3]);
        }
        gate_cnot(st, 8, 4);
        gate_cnot(st, 4, 2);
        gate_cnot(st, 2, 1);
        gate_cnot(st, 1, 8);
    }
}

// ---- kernel 0: U_fixed = fixed circuit applied to the 16 basis columns ------
__global__ void compute_ufixed(const float* __restrict__ params) {
    __shared__ float2 shU[8][4];
    int tid = threadIdx.x;
    build_fused_mats(params, shU, tid);
    __syncthreads();
    if (tid < 16) {
        float2 st[16];
#pragma unroll
        for (int k = 0; k < 16; k++)
            st[k] = make_float2((k == tid) ? 1.f : 0.f, 0.f);
        apply_layers(st, shU);
#pragma unroll
        for (int p = 0; p < 16; p++)
            g_U[p * 16 + tid] = st[p];
    }
}

// idx in [0,120) -> (p,q), p<q<16: sqrt seed + exact correction
__device__ __forceinline__ void pq_from_idx(int idx, int& p, int& q) {
    float d = 240.25f - 2.f * (float)idx;
    p = (int)(15.5f - sqrtf(d));
    if (p < 0) p = 0;
    int rem = idx - (15 * p - ((p * (p - 1)) >> 1));
    while (rem < 0) { p--; rem = idx - (15 * p - ((p * (p - 1)) >> 1)); }
    while (rem >= 15 - p) { rem -= 15 - p; p++; }
    q = p + 1 + rem;
}

// ---- build kernel: 192 blocks x 128 threads ---------------------------------
// blocks [0,64):   F-mode, 16 rows/block, 8 lanes/row
// blocks [64,192): G-mode,  8 rows/block, 16 lanes/row (2 lanes per column)
#define F_BLOCKS 64
#define G_BLOCKS 128

__global__ __launch_bounds__(128) void build_features(const float* __restrict__ a,
                                                      const float* __restrict__ b) {
    __shared__ float2 shUf[16][18];      // padded U rows
    __shared__ float2 sh_stF[16][16];    // F: u vectors, 16 rows
    __shared__ float2 sh_stG[8][16][9];  // G: B columns, 8 rows
    __shared__ float  sh_f[16][256];

    int tid = threadIdx.x;
#pragma unroll
    for (int e = tid; e < 256; e += 128)
        shUf[e >> 4][e & 15] = g_U[e];
    __syncthreads();

    bool isF = blockIdx.x < F_BLOCKS;

    if (isF) {
        int g = tid >> 3, l = tid & 7;                 // 16 rows, 8 lanes
        int row = blockIdx.x * 16 + g;
        float4 xv = *(const float4*)&a[row * 4];
        float cq[4], sq[4];
        __sincosf(0.5f * xv.x, &sq[0], &cq[0]);
        __sincosf(0.5f * xv.y, &sq[1], &cq[1]);
        __sincosf(0.5f * xv.z, &sq[2], &cq[2]);
        __sincosf(0.5f * xv.w, &sq[3], &cq[3]);

        // v_k = prod_q (bit ? s : c)   (Ry column 0)
        float v[16];
#pragma unroll
        for (int k = 0; k < 16; k++) {
            float t0 = (k & 8) ? sq[0] : cq[0];
            float t1 = (k & 4) ? sq[1] : cq[1];
            float t2 = (k & 2) ? sq[2] : cq[2];
            float t3 = (k & 1) ? sq[3] : cq[3];
            v[k] = (t0 * t1) * (t2 * t3);
        }
        // u_p = U[p,:] . v for p = l, l+8
#pragma unroll
        for (int h = 0; h < 2; h++) {
            int p = l + 8 * h;
            float ux = 0.f, uy = 0.f;
#pragma unroll
            for (int k = 0; k < 16; k++) {
                float2 Upk = shUf[p][k];
                ux += Upk.x * v[k];
                uy += Upk.y * v[k];
            }
            sh_stF[g][p] = make_float2(ux, uy);
        }
        __syncthreads();

        // diag features
#pragma unroll
        for (int h = 0; h < 2; h++) {
            int p = l + 8 * h;
            float2 u = sh_stF[g][p];
            sh_f[g][p] = u.x * u.x + u.y * u.y;
        }
        // off-diag (15 pairs per lane)
#pragma unroll
        for (int it = 0; it < 15; it++) {
            int idx = l + 8 * it;
            int p, q; pq_from_idx(idx, p, q);
            float2 up = sh_stF[g][p], uq = sh_stF[g][q];
            sh_f[g][16 + idx]  = 2.f * (up.x * uq.x + up.y * uq.y);
            sh_f[g][136 + idx] = 2.f * (up.y * uq.x - up.x * uq.y);
        }
        __syncthreads();

        // write 16 rows x 128 half2
        __half2* dst = (__half2*)g_F;
        int r0 = blockIdx.x * 16;
#pragma unroll
        for (int it = 0; it < 16; it++) {
            int flat = it * 128 + tid;
            int rl = flat >> 7, t2 = flat & 127;
            __half2 o = __floats2half2_rn(sh_f[rl][2 * t2], sh_f[rl][2 * t2 + 1]);
            dst[(size_t)(r0 + rl) * (FDIM / 2) + t2] = o;
        }
    } else {
        int g = tid >> 4, l = tid & 15;                // 8 rows, 16 lanes
        int col = l & 7, half = l >> 3;
        int row = (blockIdx.x - F_BLOCKS) * 8 + g;
        float4 xv = *(const float4*)&b[row * 4];
        float cq[4], sq[4];
        __sincosf(0.5f * xv.x, &sq[0], &cq[0]);
        __sincosf(0.5f * xv.y, &sq[1], &cq[1]);
        __sincosf(0.5f * xv.z, &sq[2], &cq[2]);
        __sincosf(0.5f * xv.w, &sq[3], &cq[3]);

        // column m = 8+col of tensor-Ry: per-qubit (f0,f1) with Ry=[[c,-s],[s,c]]
        // qubit0: m bit =1 -> f0=-s, f1=c.  qubit q>=1: mq = bit of col.
        float f0[4], f1[4];
        f0[0] = -sq[0]; f1[0] = cq[0];
#pragma unroll
        for (int q = 1; q < 4; q++) {
            int mq = (col >> (3 - q)) & 1;
            f0[q] = mq ? -sq[q] : cq[q];
            f1[q] = mq ?  cq[q] : sq[q];
        }
        float w[16];
#pragma unroll
        for (int k = 0; k < 16; k++) {
            float t0 = (k & 8) ? f1[0] : f0[0];
            float t1 = (k & 4) ? f1[1] : f0[1];
            float t2 = (k & 2) ? f1[2] : f0[2];
            float t3 = (k & 1) ? f1[3] : f0[3];
            w[k] = (t0 * t1) * (t2 * t3);
        }
        // B[p][col] = U[p,:] . w for 8 p's (this lane's half)
#pragma unroll
        for (int pi = 0; pi < 8; pi++) {
            int p = half * 8 + pi;
            float ux = 0.f, uy = 0.f;
#pragma unroll
            for (int k = 0; k < 16; k++) {
                float2 Upk = shUf[p][k];
                ux += Upk.x * w[k];
                uy += Upk.y * w[k];
            }
            sh_stG[g][p][col] = make_float2(ux, uy);
        }
        __syncthreads();

        // diag: M_pp = 1 - 2 sum_k |B[p][k]|^2  (p = l)
        {
            float s2 = 0.f;
#pragma unroll
            for (int k = 0; k < 8; k++) {
                float2 v2 = sh_stG[g][l][k];
                s2 += v2.x * v2.x + v2.y * v2.y;
            }
            sh_f[g][l] = 1.f - 2.f * s2;
        }
        // off-diag: lane-strided pairs (stride 16)
#pragma unroll
        for (int it = 0; it < 8; it++) {
            int idx = l + 16 * it;
            if (idx >= 120) break;
            int p, q; pq_from_idx(idx, p, q);
            float re = 0.f, im = 0.f;
#pragma unroll
            for (int k = 0; k < 8; k++) {
                float2 ap = sh_stG[g][p][k];
                float2 aq = sh_stG[g][q][k];
                re += ap.x * aq.x + ap.y * aq.y;
                im += ap.y * aq.x - ap.x * aq.y;
            }
            sh_f[g][16 + idx]  = -2.f * re;
            sh_f[g][136 + idx] = -2.f * im;
        }
        __syncthreads();

        // write 8 rows x 128 half2
        __half2* dst = (__half2*)g_G;
        int r0 = (blockIdx.x - F_BLOCKS) * 8;
#pragma unroll
        for (int it = 0; it < 8; it++) {
            int flat = it * 128 + tid;
            int rl = flat >> 7, t2 = flat & 127;
            __half2 o = __floats2half2_rn(sh_f[rl][2 * t2], sh_f[rl][2 * t2 + 1]);
            dst[(size_t)(r0 + rl) * (FDIM / 2) + t2] = o;
        }
    }
}

// ---- fp16 NT GEMM: full-K smem residency, 1 barrier, ldmatrix ---------------
// 64x64 tile, 256 threads (8 warps: 2m x 4n), m16n8k16, fp32 accumulate.

#define BM 64
#define BN 64
#define KPADH 264   // padded row stride in halves (528B: rows map to banks 4r)
#define GEMM_SMEM (2 * BM * KPADH * 2)

__device__ __forceinline__ void cp_async16(void* smem_dst, const void* gmem_src) {
    uint32_t s = (uint32_t)__cvta_generic_to_shared(smem_dst);
    asm volatile("cp.async.ca.shared.global [%0], [%1], 16;" :: "r"(s), "l"(gmem_src));
}

__global__ __launch_bounds__(256) void gemm_f16_abs(float* __restrict__ C) {
    extern __shared__ __half smem[];
    __half* As = smem;                 // [BM][KPADH]
    __half* Bs = smem + BM * KPADH;    // [BN][KPADH]

    int tid = threadIdx.x;
    int warp = tid >> 5, lane = tid & 31;
    int wm = warp >> 2;          // 0..1
    int wn = warp & 3;           // 0..3
    int grp = lane >> 2;         // 0..7
    int tig = lane & 3;          // 0..3

    int i0 = blockIdx.y * BM;
    int j0 = blockIdx.x * BN;

    // ---- load both full tiles (64 rows x 256 halves each) ----
#pragma unroll
    for (int it = 0; it < 8; it++) {
        int c = it * 256 + tid;
        int r = c >> 5, s = c & 31;           // 32 x 16B chunks per row
        cp_async16(&As[r * KPADH + s * 8], &g_F[(size_t)(i0 + r) * FDIM + s * 8]);
        cp_async16(&Bs[r * KPADH + s * 8], &g_G[(size_t)(j0 + r) * FDIM + s * 8]);
    }
    asm volatile("cp.async.commit_group;");
    asm volatile("cp.async.wait_group 0;");
    __syncthreads();

    // ---- ldmatrix base addresses ----
    // A x4: matrices (m0,k0),(m8,k0),(m0,k8),(m8,k8)
    int a_r = (lane & 7) + ((lane >> 3) & 1) * 8;
    int a_c = ((lane >> 4) & 1) * 8;
    uint32_t a_base[2];
#pragma unroll
    for (int mt = 0; mt < 2; mt++)
        a_base[mt] = (uint32_t)__cvta_generic_to_shared(
            &As[(wm * 32 + mt * 16 + a_r) * KPADH + a_c]);
    // B x2: matrices (n0,k0),(n0,k8); lanes 0..15 meaningful
    int b_r = lane & 7;
    int b_c = ((lane >> 3) & 1) * 8;
    uint32_t b_base[2];
#pragma unroll
    for (int nt = 0; nt < 2; nt++)
        b_base[nt] = (uint32_t)__cvta_generic_to_shared(
            &Bs[(wn * 16 + nt * 8 + b_r) * KPADH + b_c]);

    float acc[2][2][4];
#pragma unroll
    for (int mt = 0; mt < 2; mt++)
#pragma unroll
        for (int nt = 0; nt < 2; nt++)
#pragma unroll
            for (int r = 0; r < 4; r++) acc[mt][nt][r] = 0.f;

    // ---- mainloop: 16 k16 steps, no barriers ----
#pragma unroll
    for (int k16 = 0; k16 < FDIM / 16; k16++) {
        uint32_t koff = (uint32_t)(k16 * 32);   // 16 halves = 32 bytes
        uint32_t afr[2][4], bfr[2][2];
#pragma unroll
        for (int mt = 0; mt < 2; mt++) {
            asm volatile(
                "ldmatrix.sync.aligned.m8n8.x4.shared.b16 {%0,%1,%2,%3}, [%4];"
                : "=r"(afr[mt][0]), "=r"(afr[mt][1]),
                  "=r"(afr[mt][2]), "=r"(afr[mt][3])
                : "r"(a_base[mt] + koff));
        }
#pragma unroll
        for (int nt = 0; nt < 2; nt++) {
            asm volatile(
                "ldmatrix.sync.aligned.m8n8.x2.shared.b16 {%0,%1}, [%2];"
                : "=r"(bfr[nt][0]), "=r"(bfr[nt][1])
                : "r"(b_base[nt] + koff));
        }
#pragma unroll
        for (int mt = 0; mt < 2; mt++)
#pragma unroll
            for (int nt = 0; nt < 2; nt++) {
                asm volatile(
                    "mma.sync.aligned.m16n8k16.row.col.f32.f16.f16.f32 "
                    "{%0,%1,%2,%3}, {%4,%5,%6,%7}, {%8,%9}, {%0,%1,%2,%3};"
                    : "+f"(acc[mt][nt][0]), "+f"(acc[mt][nt][1]),
                      "+f"(acc[mt][nt][2]), "+f"(acc[mt][nt][3])
                    : "r"(afr[mt][0]), "r"(afr[mt][1]),
                      "r"(afr[mt][2]), "r"(afr[mt][3]),
                      "r"(bfr[nt][0]), "r"(bfr[nt][1]));
            }
    }

    // ---- epilogue ----
#pragma unroll
    for (int mt = 0; mt < 2; mt++) {
        int rowg = i0 + wm * 32 + mt * 16 + grp;
#pragma unroll
        for (int nt = 0; nt < 2; nt++) {
            int colg = j0 + wn * 16 + nt * 8 + 2 * tig;
            float2 o0 = make_float2(fabsf(acc[mt][nt][0]), fabsf(acc[mt][nt][1]));
            float2 o1 = make_float2(fabsf(acc[mt][nt][2]), fabsf(acc[mt][nt][3]));
            *(float2*)&C[(size_t)rowg * NROWS + colg] = o0;
            *(float2*)&C[(size_t)(rowg + 8) * NROWS + colg] = o1;
        }
    }
}

// ---------------------------------------------------------------------------
extern "C" void kernel_launch(void* const* d_in, const int* in_sizes, int n_in,
                              void* d_out, int out_size) {
    const float* a = (const float*)d_in[0];       // [1024,4]
    const float* b = (const float*)d_in[1];       // [1024,4]
    const float* params = (const float*)d_in[2];  // [2,4,3]
    float* out = (float*)d_out;                   // [1024,1024]

    cudaFuncSetAttribute(gemm_f16_abs,
                         cudaFuncAttributeMaxDynamicSharedMemorySize, GEMM_SMEM);

    compute_ufixed<<<1, 32>>>(params);
    build_features<<<F_BLOCKS + G_BLOCKS, 128>>>(a, b);

    dim3 grid(NROWS / BN, NROWS / BM);   // (16, 16) = 256 blocks
    gemm_f16_abs<<<grid, 256, GEMM_SMEM>>>(out);
}

// round 9
// speedup vs baseline: 6.5647x; 1.2935x over previous
#include <cuda_runtime.h>
#include <cuda_fp16.h>
#include <math.h>
#include <stdint.h>

// ---------------------------------------------------------------------------
// QuantumKernelMethod: 4 qubits, 2 layers.
// z(i,j) = | u_i^H M_j u_i |, u_i = A(a_i)|0>, M_j = A(b_j) Z0 A(b_j)^H.
// A(x) = U_fixed * (tensor_q Ry(x_q)); U_fixed computed in-block (parallel,
// 16 cols x 8 pairs = 128 threads). M = I - 2 B B^H, B = A[:,8:16].
// Gram = | F[1024x256] * G^T | via fp16 MMA (fp32 accumulate), full-K smem.
// ---------------------------------------------------------------------------

#define NROWS 1024
#define FDIM 256

__device__ __align__(16) __half g_F[NROWS * FDIM];
__device__ __align__(16) __half g_G[NROWS * FDIM];

// fused U(l,i) = Rz(c) Ry(b) Rx(a); lanes 0..7 compute one each
__device__ __forceinline__ void build_fused_mats(const float* params,
                                                 float2 (*shU)[4], int tid) {
    if (tid < 8) {
        float a = params[tid * 3 + 0], b = params[tid * 3 + 1], c = params[tid * 3 + 2];
        float sa, ca, sb, cb, sc, cc;
        __sincosf(0.5f * a, &sa, &ca);
        __sincosf(0.5f * b, &sb, &cb);
        __sincosf(0.5f * c, &sc, &cc);
        float2 m00 = make_float2(cb * ca,  sb * sa);
        float2 m01 = make_float2(-sb * ca, -cb * sa);
        float2 m10 = make_float2(sb * ca, -cb * sa);
        float2 m11 = make_float2(cb * ca, -sb * sa);
        shU[tid][0] = make_float2(cc * m00.x + sc * m00.y, cc * m00.y - sc * m00.x);
        shU[tid][1] = make_float2(cc * m01.x + sc * m01.y, cc * m01.y - sc * m01.x);
        shU[tid][2] = make_float2(cc * m10.x - sc * m10.y, cc * m10.y + sc * m10.x);
        shU[tid][3] = make_float2(cc * m11.x - sc * m11.y, cc * m11.y + sc * m11.x);
    }
}

// CNOT ring (0,1)(1,2)(2,3)(3,0) as a basis-index permutation
__device__ __forceinline__ int cnot_perm(int idx) {
    if (idx & 8) idx ^= 4;
    if (idx & 4) idx ^= 2;
    if (idx & 2) idx ^= 1;
    if (idx & 1) idx ^= 8;
    return idx;
}

// idx in [0,120) -> (p,q), p<q<16: sqrt seed + exact correction
__device__ __forceinline__ void pq_from_idx(int idx, int& p, int& q) {
    float d = 240.25f - 2.f * (float)idx;
    p = (int)(15.5f - sqrtf(d));
    if (p < 0) p = 0;
    int rem = idx - (15 * p - ((p * (p - 1)) >> 1));
    while (rem < 0) { p--; rem = idx - (15 * p - ((p * (p - 1)) >> 1)); }
    while (rem >= 15 - p) { rem -= 15 - p; p++; }
    q = p + 1 + rem;
}

// ---- build kernel: 192 blocks x 128 threads ---------------------------------
// blocks [0,64):   F-mode, 16 rows/block, 8 lanes/row
// blocks [64,192): G-mode,  8 rows/block, 16 lanes/row
#define F_BLOCKS 64
#define G_BLOCKS 128

__global__ __launch_bounds__(128) void build_features(const float* __restrict__ a,
                                                      const float* __restrict__ b,
                                                      const float* __restrict__ params) {
    __shared__ float2 shU[8][4];
    __shared__ float2 shS[16][17];       // [column k][amp p] = U_fixed[p][k]
    __shared__ float2 sh_stF[16][16];    // F: u vectors, 16 rows
    __shared__ float2 sh_stG[8][16][9];  // G: B columns, 8 rows
    __shared__ float  sh_f[16][256];

    int tid = threadIdx.x;
    build_fused_mats(params, shU, tid);

    // ---- in-block parallel U_fixed: 16 columns x 8 pairs ----
    {
        int ucol = tid & 15, pr = tid >> 4;   // pr in 0..7
        // init: column ucol = e_ucol; this thread owns amps 2pr, 2pr+1
#pragma unroll
        for (int h = 0; h < 2; h++) {
            int amp = pr * 2 + h;
            shS[ucol][amp] = make_float2((amp == ucol) ? 1.f : 0.f, 0.f);
        }
        __syncthreads();

#pragma unroll
        for (int l = 0; l < 2; l++) {
#pragma unroll
            for (int i = 0; i < 4; i++) {
                int m = 8 >> i;
                int lo = pr & (m - 1);
                int idx0 = ((pr & ~(m - 1)) << 1) | lo;
                int idx1 = idx0 | m;

                float2 x0 = shS[ucol][idx0];
                float2 x1 = shS[ucol][idx1];
                float2 U00 = shU[l * 4 + i][0], U01 = shU[l * 4 + i][1];
                float2 U10 = shU[l * 4 + i][2], U11 = shU[l * 4 + i][3];
                float2 n0, n1;
                n0.x = U00.x * x0.x - U00.y * x0.y + U01.x * x1.x - U01.y * x1.y;
                n0.y = U00.x * x0.y + U00.y * x0.x + U01.x * x1.y + U01.y * x1.x;
                n1.x = U10.x * x0.x - U10.y * x0.y + U11.x * x1.x - U11.y * x1.y;
                n1.y = U10.x * x0.y + U10.y * x0.x + U11.x * x1.y + U11.y * x1.x;

                if (i == 3) {
                    // fold CNOT-ring permutation into this write (scatter)
                    __syncthreads();   // everyone finished reading old state
                    shS[ucol][cnot_perm(idx0)] = n0;
                    shS[ucol][cnot_perm(idx1)] = n1;
                } else {
                    shS[ucol][idx0] = n0;
                    shS[ucol][idx1] = n1;
                }
                __syncthreads();
            }
        }
    }
    // shS[k][p] now holds U_fixed[p][k]

    bool isF = blockIdx.x < F_BLOCKS;

    if (isF) {
        int g = tid >> 3, l = tid & 7;                 // 16 rows, 8 lanes
        int row = blockIdx.x * 16 + g;
        float4 xv = *(const float4*)&a[row * 4];
        float cq[4], sq[4];
        __sincosf(0.5f * xv.x, &sq[0], &cq[0]);
        __sincosf(0.5f * xv.y, &sq[1], &cq[1]);
        __sincosf(0.5f * xv.z, &sq[2], &cq[2]);
        __sincosf(0.5f * xv.w, &sq[3], &cq[3]);

        // v_k = prod_q (bit ? s : c)   (tensor-Ry column 0)
        float v[16];
#pragma unroll
        for (int k = 0; k < 16; k++) {
            float t0 = (k & 8) ? sq[0] : cq[0];
            float t1 = (k & 4) ? sq[1] : cq[1];
            float t2 = (k & 2) ? sq[2] : cq[2];
            float t3 = (k & 1) ? sq[3] : cq[3];
            v[k] = (t0 * t1) * (t2 * t3);
        }
        // u_p = sum_k U[p][k] v_k = sum_k shS[k][p] v_k, for p = l, l+8
#pragma unroll
        for (int h = 0; h < 2; h++) {
            int p = l + 8 * h;
            float ux = 0.f, uy = 0.f;
#pragma unroll
            for (int k = 0; k < 16; k++) {
                float2 Upk = shS[k][p];
                ux += Upk.x * v[k];
                uy += Upk.y * v[k];
            }
            sh_stF[g][p] = make_float2(ux, uy);
        }
        __syncthreads();

        // diag features
#pragma unroll
        for (int h = 0; h < 2; h++) {
            int p = l + 8 * h;
            float2 u = sh_stF[g][p];
            sh_f[g][p] = u.x * u.x + u.y * u.y;
        }
        // off-diag (15 pairs per lane)
#pragma unroll
        for (int it = 0; it < 15; it++) {
            int idx = l + 8 * it;
            int p, q; pq_from_idx(idx, p, q);
            float2 up = sh_stF[g][p], uq = sh_stF[g][q];
            sh_f[g][16 + idx]  = 2.f * (up.x * uq.x + up.y * uq.y);
            sh_f[g][136 + idx] = 2.f * (up.y * uq.x - up.x * uq.y);
        }
        __syncthreads();

        // write 16 rows x 128 half2
        __half2* dst = (__half2*)g_F;
        int r0 = blockIdx.x * 16;
#pragma unroll
        for (int it = 0; it < 16; it++) {
            int flat = it * 128 + tid;
            int rl = flat >> 7, t2 = flat & 127;
            __half2 o = __floats2half2_rn(sh_f[rl][2 * t2], sh_f[rl][2 * t2 + 1]);
            dst[(size_t)(r0 + rl) * (FDIM / 2) + t2] = o;
        }
    } else {
        int g = tid >> 4, l = tid & 15;                // 8 rows, 16 lanes
        int col = l & 7, half = l >> 3;
        int row = (blockIdx.x - F_BLOCKS) * 8 + g;
        float4 xv = *(const float4*)&b[row * 4];
        float cq[4], sq[4];
        __sincosf(0.5f * xv.x, &sq[0], &cq[0]);
        __sincosf(0.5f * xv.y, &sq[1], &cq[1]);
        __sincosf(0.5f * xv.z, &sq[2], &cq[2]);
        __sincosf(0.5f * xv.w, &sq[3], &cq[3]);

        // column m = 8+col of tensor-Ry (Ry = [[c,-s],[s,c]])
        float f0[4], f1[4];
        f0[0] = -sq[0]; f1[0] = cq[0];
#pragma unroll
        for (int q = 1; q < 4; q++) {
            int mq = (col >> (3 - q)) & 1;
            f0[q] = mq ? -sq[q] : cq[q];
            f1[q] = mq ?  cq[q] : sq[q];
        }
        float w[16];
#pragma unroll
        for (int k = 0; k < 16; k++) {
            float t0 = (k & 8) ? f1[0] : f0[0];
            float t1 = (k & 4) ? f1[1] : f0[1];
            float t2 = (k & 2) ? f1[2] : f0[2];
            float t3 = (k & 1) ? f1[3] : f0[3];
            w[k] = (t0 * t1) * (t2 * t3);
        }
        // B[p][col] = sum_k shS[k][p] w_k for 8 p's (this lane's half)
#pragma unroll
        for (int pi = 0; pi < 8; pi++) {
            int p = half * 8 + pi;
            float ux = 0.f, uy = 0.f;
#pragma unroll
            for (int k = 0; k < 16; k++) {
                float2 Upk = shS[k][p];
                ux += Upk.x * w[k];
                uy += Upk.y * w[k];
            }
            sh_stG[g][p][col] = make_float2(ux, uy);
        }
        __syncthreads();

        // diag: M_pp = 1 - 2 sum_k |B[p][k]|^2  (p = l)
        {
            float s2 = 0.f;
#pragma unroll
            for (int k = 0; k < 8; k++) {
                float2 v2 = sh_stG[g][l][k];
                s2 += v2.x * v2.x + v2.y * v2.y;
            }
            sh_f[g][l] = 1.f - 2.f * s2;
        }
        // off-diag: lane-strided pairs (stride 16)
#pragma unroll
        for (int it = 0; it < 8; it++) {
            int idx = l + 16 * it;
            if (idx >= 120) break;
            int p, q; pq_from_idx(idx, p, q);
            float re = 0.f, im = 0.f;
#pragma unroll
            for (int k = 0; k < 8; k++) {
                float2 ap = sh_stG[g][p][k];
                float2 aq = sh_stG[g][q][k];
                re += ap.x * aq.x + ap.y * aq.y;
                im += ap.y * aq.x - ap.x * aq.y;
            }
            sh_f[g][16 + idx]  = -2.f * re;
            sh_f[g][136 + idx] = -2.f * im;
        }
        __syncthreads();

        // write 8 rows x 128 half2
        __half2* dst = (__half2*)g_G;
        int r0 = (blockIdx.x - F_BLOCKS) * 8;
#pragma unroll
        for (int it = 0; it < 8; it++) {
            int flat = it * 128 + tid;
            int rl = flat >> 7, t2 = flat & 127;
            __half2 o = __floats2half2_rn(sh_f[rl][2 * t2], sh_f[rl][2 * t2 + 1]);
            dst[(size_t)(r0 + rl) * (FDIM / 2) + t2] = o;
        }
    }
}

// ---- fp16 NT GEMM: full-K smem residency, 1 barrier, ldmatrix ---------------
// 64x64 tile, 256 threads (8 warps: 2m x 4n), m16n8k16, fp32 accumulate.

#define BM 64
#define BN 64
#define KPADH 264   // padded row stride in halves
#define GEMM_SMEM (2 * BM * KPADH * 2)

__device__ __forceinline__ void cp_async16(void* smem_dst, const void* gmem_src) {
    uint32_t s = (uint32_t)__cvta_generic_to_shared(smem_dst);
    asm volatile("cp.async.ca.shared.global [%0], [%1], 16;" :: "r"(s), "l"(gmem_src));
}

__global__ __launch_bounds__(256) void gemm_f16_abs(float* __restrict__ C) {
    extern __shared__ __half smem[];
    __half* As = smem;                 // [BM][KPADH]
    __half* Bs = smem + BM * KPADH;    // [BN][KPADH]

    int tid = threadIdx.x;
    int warp = tid >> 5, lane = tid & 31;
    int wm = warp >> 2;          // 0..1
    int wn = warp & 3;           // 0..3
    int grp = lane >> 2;         // 0..7
    int tig = lane & 3;          // 0..3

    int i0 = blockIdx.y * BM;
    int j0 = blockIdx.x * BN;

    // ---- load both full tiles (64 rows x 256 halves each) ----
#pragma unroll
    for (int it = 0; it < 8; it++) {
        int c = it * 256 + tid;
        int r = c >> 5, s = c & 31;
        cp_async16(&As[r * KPADH + s * 8], &g_F[(size_t)(i0 + r) * FDIM + s * 8]);
        cp_async16(&Bs[r * KPADH + s * 8], &g_G[(size_t)(j0 + r) * FDIM + s * 8]);
    }
    asm volatile("cp.async.commit_group;");
    asm volatile("cp.async.wait_group 0;");
    __syncthreads();

    // ---- ldmatrix base addresses ----
    int a_r = (lane & 7) + ((lane >> 3) & 1) * 8;
    int a_c = ((lane >> 4) & 1) * 8;
    uint32_t a_base[2];
#pragma unroll
    for (int mt = 0; mt < 2; mt++)
        a_base[mt] = (uint32_t)__cvta_generic_to_shared(
            &As[(wm * 32 + mt * 16 + a_r) * KPADH + a_c]);
    int b_r = lane & 7;
    int b_c = ((lane >> 3) & 1) * 8;
    uint32_t b_base[2];
#pragma unroll
    for (int nt = 0; nt < 2; nt++)
        b_base[nt] = (uint32_t)__cvta_generic_to_shared(
            &Bs[(wn * 16 + nt * 8 + b_r) * KPADH + b_c]);

    float acc[2][2][4];
#pragma unroll
    for (int mt = 0; mt < 2; mt++)
#pragma unroll
        for (int nt = 0; nt < 2; nt++)
#pragma unroll
            for (int r = 0; r < 4; r++) acc[mt][nt][r] = 0.f;

    // ---- mainloop: 16 k16 steps, no barriers ----
#pragma unroll
    for (int k16 = 0; k16 < FDIM / 16; k16++) {
        uint32_t koff = (uint32_t)(k16 * 32);
        uint32_t afr[2][4], bfr[2][2];
#pragma unroll
        for (int mt = 0; mt < 2; mt++) {
            asm volatile(
                "ldmatrix.sync.aligned.m8n8.x4.shared.b16 {%0,%1,%2,%3}, [%4];"
                : "=r"(afr[mt][0]), "=r"(afr[mt][1]),
                  "=r"(afr[mt][2]), "=r"(afr[mt][3])
                : "r"(a_base[mt] + koff));
        }
#pragma unroll
        for (int nt = 0; nt < 2; nt++) {
            asm volatile(
                "ldmatrix.sync.aligned.m8n8.x2.shared.b16 {%0,%1}, [%2];"
                : "=r"(bfr[nt][0]), "=r"(bfr[nt][1])
                : "r"(b_base[nt] + koff));
        }
#pragma unroll
        for (int mt = 0; mt < 2; mt++)
#pragma unroll
            for (int nt = 0; nt < 2; nt++) {
                asm volatile(
                    "mma.sync.aligned.m16n8k16.row.col.f32.f16.f16.f32 "
                    "{%0,%1,%2,%3}, {%4,%5,%6,%7}, {%8,%9}, {%0,%1,%2,%3};"
                    : "+f"(acc[mt][nt][0]), "+f"(acc[mt][nt][1]),
                      "+f"(acc[mt][nt][2]), "+f"(acc[mt][nt][3])
                    : "r"(afr[mt][0]), "r"(afr[mt][1]),
                      "r"(afr[mt][2]), "r"(afr[mt][3]),
                      "r"(bfr[nt][0]), "r"(bfr[nt][1]));
            }
    }

    // ---- epilogue ----
#pragma unroll
    for (int mt = 0; mt < 2; mt++) {
        int rowg = i0 + wm * 32 + mt * 16 + grp;
#pragma unroll
        for (int nt = 0; nt < 2; nt++) {
            int colg = j0 + wn * 16 + nt * 8 + 2 * tig;
            float2 o0 = make_float2(fabsf(acc[mt][nt][0]), fabsf(acc[mt][nt][1]));
            float2 o1 = make_float2(fabsf(acc[mt][nt][2]), fabsf(acc[mt][nt][3]));
            *(float2*)&C[(size_t)rowg * NROWS + colg] = o0;
            *(float2*)&C[(size_t)(rowg + 8) * NROWS + colg] = o1;
        }
    }
}

// ---------------------------------------------------------------------------
extern "C" void kernel_launch(void* const* d_in, const int* in_sizes, int n_in,
                              void* d_out, int out_size) {
    const float* a = (const float*)d_in[0];       // [1024,4]
    const float* b = (const float*)d_in[1];       // [1024,4]
    const float* params = (const float*)d_in[2];  // [2,4,3]
    float* out = (float*)d_out;                   // [1024,1024]

    cudaFuncSetAttribute(gemm_f16_abs,
                         cudaFuncAttributeMaxDynamicSharedMemorySize, GEMM_SMEM);

    build_features<<<F_BLOCKS + G_BLOCKS, 128>>>(a, b, params);

    dim3 grid(NROWS / BN, NROWS / BM);   // (16, 16) = 256 blocks
    gemm_f16_abs<<<grid, 256, GEMM_SMEM>>>(out);
}